// round 1
// baseline (speedup 1.0000x reference)
#include <cuda_runtime.h>
#include <math.h>

// Problem constants
#define B_  8
#define S_  4096
#define E_  1024
#define H_  16
#define D_  64
#define M1  (B_ * S_)        // 32768 rows for img projections
#define M2  (B_ * 2 * S_)    // 65536 rows for final projection

// Scratch (device globals — no allocation allowed in kernel_launch)
__device__ float g_kit[M1 * E_];     // 128 MB
__device__ float g_vit[M1 * E_];     // 128 MB
__device__ float g_kti[B_ * E_];
__device__ float g_vti[B_ * E_];
__device__ float g_cat[M2 * E_];     // 256 MB  (concat of img_out, text_out)

// ---------------------------------------------------------------------------
// Classic 128x128x8 fp32 SGEMM, 8x8 per thread, 256 threads.
// C[M,N] = A[M,K] @ W[K,N] + bias[N]   (all row-major; M%128==0, N%128==0, K%8==0)
// ---------------------------------------------------------------------------
__global__ __launch_bounds__(256)
void sgemm128(const float* __restrict__ A, const float* __restrict__ W,
              const float* __restrict__ bias, float* __restrict__ C,
              int M, int N, int K)
{
    constexpr int BM = 128, BN = 128, BK = 8, TM = 8, TN = 8;
    const int tid  = threadIdx.x;
    const int brow = blockIdx.x;   // M tiles
    const int bcol = blockIdx.y;   // N tiles

    __shared__ float As[BK][BM];
    __shared__ float Bs[BK][BN];

    const int threadRow = tid / (BN / TN);   // 0..15
    const int threadCol = tid % (BN / TN);   // 0..15

    const int aRow = tid / (BK / 4);         // 0..127
    const int aCol = (tid % (BK / 4)) * 4;   // 0 or 4
    const int bRow = tid / (BN / 4);         // 0..7
    const int bCol = (tid % (BN / 4)) * 4;   // 0..124

    const float* Aptr = A + (size_t)brow * BM * K;
    const float* Wptr = W + (size_t)bcol * BN;

    float acc[TM][TN] = {};

    for (int k0 = 0; k0 < K; k0 += BK) {
        float4 av = *(const float4*)(Aptr + (size_t)aRow * K + k0 + aCol);
        As[aCol + 0][aRow] = av.x;
        As[aCol + 1][aRow] = av.y;
        As[aCol + 2][aRow] = av.z;
        As[aCol + 3][aRow] = av.w;
        float4 bv = *(const float4*)(Wptr + (size_t)(k0 + bRow) * N + bCol);
        *(float4*)&Bs[bRow][bCol] = bv;
        __syncthreads();

        #pragma unroll
        for (int k = 0; k < BK; k++) {
            float regM[TM], regN[TN];
            #pragma unroll
            for (int i = 0; i < TM; i++) regM[i] = As[k][threadRow * TM + i];
            #pragma unroll
            for (int j = 0; j < TN; j++) regN[j] = Bs[k][threadCol * TN + j];
            #pragma unroll
            for (int i = 0; i < TM; i++)
                #pragma unroll
                for (int j = 0; j < TN; j++)
                    acc[i][j] += regM[i] * regN[j];
        }
        __syncthreads();
    }

    float* Cptr = C + (size_t)brow * BM * N + (size_t)bcol * BN;
    #pragma unroll
    for (int i = 0; i < TM; i++) {
        const int r = threadRow * TM + i;
        #pragma unroll
        for (int j = 0; j < TN; j += 4) {
            const int c = threadCol * TN + j;
            float4 o;
            o.x = acc[i][j + 0] + bias[bcol * BN + c + 0];
            o.y = acc[i][j + 1] + bias[bcol * BN + c + 1];
            o.z = acc[i][j + 2] + bias[bcol * BN + c + 2];
            o.w = acc[i][j + 3] + bias[bcol * BN + c + 3];
            *(float4*)(Cptr + (size_t)r * N + c) = o;
        }
    }
}

// ---------------------------------------------------------------------------
// Tiny projections: k_ti = text @ W_kti + b, v_ti = text @ W_vti + b.
// grid (E/256, B), 256 threads. One thread per output column.
// ---------------------------------------------------------------------------
__global__ __launch_bounds__(256)
void small_proj(const float* __restrict__ text,
                const float* __restrict__ Wk, const float* __restrict__ bk,
                const float* __restrict__ Wv, const float* __restrict__ bv)
{
    const int b = blockIdx.y;
    const int n = blockIdx.x * 256 + threadIdx.x;
    __shared__ float ts[E_];
    for (int i = threadIdx.x; i < E_; i += 256) ts[i] = text[b * E_ + i];
    __syncthreads();
    float accK = 0.f, accV = 0.f;
    for (int k = 0; k < E_; k++) {
        const float t = ts[k];
        accK += t * Wk[(size_t)k * E_ + n];
        accV += t * Wv[(size_t)k * E_ + n];
    }
    g_kti[b * E_ + n] = accK + bk[n];
    g_vti[b * E_ + n] = accV + bv[n];
}

// ---------------------------------------------------------------------------
// Fused per-position cross-attention (both directions) over the HEADS axis.
// One block per (b, n). 256 threads.
//   img_att  = softmax( reshape(text[b]) @ reshape(k_it[b,n])^T / sqrt(D) )   [16x16]
//   img_out  = img_att @ reshape(v_it[b,n])                                   [16x64]
//   text_att = softmax( reshape(img[b,n]) @ reshape(k_ti[b])^T / sqrt(D) )
//   text_out = text_att @ reshape(v_ti[b])
// Writes into g_cat rows (b*2S + n) and (b*2S + S + n).
// ---------------------------------------------------------------------------
__global__ __launch_bounds__(256)
void attention_pos(const float* __restrict__ img, const float* __restrict__ text)
{
    const int n = blockIdx.x;
    const int b = blockIdx.y;
    const int tid = threadIdx.x;

    constexpr int PD = 65;   // padded head stride (conflict-free LDS)
    __shared__ float xs[E_];          // img[b,n]
    __shared__ float ks[H_ * PD];     // k_it[b,n], padded
    __shared__ float vs[E_];          // v_it[b,n]
    __shared__ float txs[E_];         // text[b]
    __shared__ float ktis[H_ * PD];   // k_ti[b], padded
    __shared__ float vtis[E_];        // v_ti[b]
    __shared__ float att1[H_][H_];
    __shared__ float att2[H_][H_];

    const size_t rowOff = ((size_t)b * S_ + n) * E_;
    for (int i = tid; i < E_; i += 256) {
        const int l = i >> 6, j = i & 63;
        xs[i]  = img[rowOff + i];
        ks[l * PD + j]   = g_kit[rowOff + i];
        vs[i]  = g_vit[rowOff + i];
        txs[i] = text[b * E_ + i];
        ktis[l * PD + j] = g_kti[b * E_ + i];
        vtis[i] = g_vti[b * E_ + i];
    }
    __syncthreads();

    // scores: thread t -> (q = t>>4, l = t&15); row q occupies 16 contiguous lanes
    const int q = tid >> 4;
    const int l = tid & 15;
    const float inv_sqrt_d = 0.125f;

    float s1 = 0.f, s2 = 0.f;
    #pragma unroll 16
    for (int j = 0; j < D_; j++) {
        s1 += txs[q * 64 + j] * ks[l * PD + j];
        s2 += xs[q * 64 + j]  * ktis[l * PD + j];
    }
    s1 *= inv_sqrt_d;
    s2 *= inv_sqrt_d;

    // softmax over l within each 16-lane group
    float m1 = s1, m2 = s2;
    #pragma unroll
    for (int o = 8; o > 0; o >>= 1) {
        m1 = fmaxf(m1, __shfl_xor_sync(0xffffffffu, m1, o));
        m2 = fmaxf(m2, __shfl_xor_sync(0xffffffffu, m2, o));
    }
    float e1 = expf(s1 - m1), e2 = expf(s2 - m2);
    float z1 = e1, z2 = e2;
    #pragma unroll
    for (int o = 8; o > 0; o >>= 1) {
        z1 += __shfl_xor_sync(0xffffffffu, z1, o);
        z2 += __shfl_xor_sync(0xffffffffu, z2, o);
    }
    att1[q][l] = e1 / z1;
    att2[q][l] = e2 / z2;
    __syncthreads();

    // outputs: o[q][d] = sum_l att[q][l] * v[l][d]
    float* cat_img  = g_cat + (((size_t)b * 2 * S_) + n) * E_;
    float* cat_text = g_cat + (((size_t)b * 2 * S_) + S_ + n) * E_;
    #pragma unroll
    for (int rep = 0; rep < 4; rep++) {
        const int idx = rep * 256 + tid;
        const int qq = idx >> 6, d = idx & 63;
        float o1 = 0.f, o2 = 0.f;
        #pragma unroll
        for (int ll = 0; ll < H_; ll++) {
            o1 += att1[qq][ll] * vs[ll * 64 + d];
            o2 += att2[qq][ll] * vtis[ll * 64 + d];
        }
        cat_img[idx]  = o1;
        cat_text[idx] = o2;
    }
}

// ---------------------------------------------------------------------------
extern "C" void kernel_launch(void* const* d_in, const int* in_sizes, int n_in,
                              void* d_out, int out_size)
{
    const float* img   = (const float*)d_in[0];
    const float* text  = (const float*)d_in[1];
    const float* W_kit = (const float*)d_in[2];
    const float* b_kit = (const float*)d_in[3];
    const float* W_vit = (const float*)d_in[4];
    const float* b_vit = (const float*)d_in[5];
    const float* W_kti = (const float*)d_in[6];
    const float* b_kti = (const float*)d_in[7];
    const float* W_vti = (const float*)d_in[8];
    const float* b_vti = (const float*)d_in[9];
    const float* W_out = (const float*)d_in[10];
    const float* b_out = (const float*)d_in[11];
    float* out = (float*)d_out;

    float *kit, *vit, *cat;
    cudaGetSymbolAddress((void**)&kit, g_kit);
    cudaGetSymbolAddress((void**)&vit, g_vit);
    cudaGetSymbolAddress((void**)&cat, g_cat);

    // 1) tiny text projections
    small_proj<<<dim3(E_ / 256, B_), 256>>>(text, W_kti, b_kti, W_vti, b_vti);

    // 2,3) big img projections
    sgemm128<<<dim3(M1 / 128, E_ / 128), 256>>>(img, W_kit, b_kit, kit, M1, E_, E_);
    sgemm128<<<dim3(M1 / 128, E_ / 128), 256>>>(img, W_vit, b_vit, vit, M1, E_, E_);

    // 4) fused per-position attention -> concat buffer
    attention_pos<<<dim3(S_, B_), 256>>>(img, text);

    // 5) final projection -> output
    sgemm128<<<dim3(M2 / 128, E_ / 128), 256>>>(cat, W_out, b_out, out, M2, E_, E_);
}

// round 3
// speedup vs baseline: 2.7160x; 2.7160x over previous
#include <cuda_runtime.h>
#include <cstdint>
#include <math.h>

// Problem constants
#define B_   8
#define S_   4096
#define E_   1024
#define H_   16
#define D_   64
#define M1   (B_ * S_)        // 32768
#define M2   (B_ * 2 * S_)    // 65536
#define KDIM 1024
#define NDIM 1024

// Scratch (device globals)
__device__ float g_a32[M1 * E_];    // img rounded to tf32
__device__ float g_kit[M1 * E_];
__device__ float g_vit[M1 * E_];
__device__ float g_kti[B_ * E_];
__device__ float g_vti[B_ * E_];
__device__ float g_cat[M2 * E_];    // concat, tf32-rounded
__device__ float g_wkT[E_ * E_];    // W^T (tf32-rounded), [N,K] K-major
__device__ float g_wvT[E_ * E_];
__device__ float g_woT[E_ * E_];

// ---------------------------------------------------------------------------
// helpers
// ---------------------------------------------------------------------------
__device__ __forceinline__ uint32_t smem_u32(const void* p) {
    uint32_t a;
    asm("{ .reg .u64 t; cvta.to.shared.u64 t, %1; cvt.u32.u64 %0, t; }" : "=r"(a) : "l"(p));
    return a;
}
__device__ __forceinline__ float tf32r(float x) {
    uint32_t u; asm("cvt.rna.tf32.f32 %0, %1;" : "=r"(u) : "f"(x));
    return __uint_as_float(u);
}
__device__ __forceinline__ void cp_async16(uint32_t dst, const void* src) {
    asm volatile("cp.async.cg.shared.global [%0], [%1], 16;" :: "r"(dst), "l"(src) : "memory");
}
__device__ __forceinline__ void cp_commit() {
    asm volatile("cp.async.commit_group;" ::: "memory");
}
template <int N> __device__ __forceinline__ void cp_wait() {
    asm volatile("cp.async.wait_group %0;" :: "n"(N) : "memory");
}
__device__ __forceinline__ void mma_tf32(float* d, const uint32_t* a, const uint32_t* b) {
    asm volatile(
        "mma.sync.aligned.m16n8k8.row.col.f32.tf32.tf32.f32 "
        "{%0,%1,%2,%3}, {%4,%5,%6,%7}, {%8,%9}, {%0,%1,%2,%3};"
        : "+f"(d[0]), "+f"(d[1]), "+f"(d[2]), "+f"(d[3])
        : "r"(a[0]), "r"(a[1]), "r"(a[2]), "r"(a[3]), "r"(b[0]), "r"(b[1]));
}

// ---------------------------------------------------------------------------
// Tensor-core tf32 GEMM:  C[M,1024] = A[M,1024] @ Wt[1024,1024]^T + bias
//   A  row-major [M,K]  (tf32-rounded fp32 bits)
//   Wt row-major [N,K]  (tf32-rounded)
// Block tile 128(m) x 128(n), K in 32-wide stages, 4-stage cp.async pipeline.
// mma operands swapped: mma-A = Wt tile (n-rows), mma-B = act tile (m-cols),
// accumulators hold Ct[n][m]; epilogue transposes via smem.
// 256 threads = 8 warps, warp tile n64 x m32. grid (N/128, M/128).
// ---------------------------------------------------------------------------
#define STG 4
#define ROWSTRIDE 36                       // floats per smem row (conflict-free)
#define TILE_BYTES (128 * ROWSTRIDE * 4)   // 18432
#define STAGE_BYTES (2 * TILE_BYTES)       // Wt tile + act tile
#define GEMM_SMEM (STG * STAGE_BYTES)      // 147456

__global__ __launch_bounds__(256, 1)
void gemm_tc(const float* __restrict__ A, const float* __restrict__ Wt,
             const float* __restrict__ bias, float* __restrict__ C, int Mrows)
{
    extern __shared__ char smem[];
    const uint32_t sbase = smem_u32(smem);
    const int tid = threadIdx.x;
    const int wid = tid >> 5, lane = tid & 31;
    const int g = lane >> 2, tg = lane & 3;

    const int ntile = blockIdx.x, mtile = blockIdx.y;
    const int nbase = (wid >> 2) * 64;   // warp n-offset (0 or 64)
    const int mbase = (wid & 3) * 32;    // warp m-offset (0,32,64,96)

    const float* Wrow = Wt + (size_t)ntile * 128 * KDIM;
    const float* Arow = A + (size_t)mtile * 128 * KDIM;

    // staging geometry: per stage, per operand: 128 rows x 8 chunks(16B).
    // 1024 chunks / 256 threads = 4 chunks per thread per operand.
    int srcOff[4];      // element offset into [row, k-chunk]
    uint32_t dstOff[4]; // byte offset into tile
    #pragma unroll
    for (int i = 0; i < 4; i++) {
        int c = tid + i * 256;
        int r = c >> 3, c4 = c & 7;
        srcOff[i] = r * KDIM + c4 * 4;
        dstOff[i] = (uint32_t)(r * (ROWSTRIDE * 4) + c4 * 16);
    }

    auto load_stage = [&](int it) {
        const uint32_t wbuf = sbase + (it % STG) * STAGE_BYTES;
        const uint32_t abuf = wbuf + TILE_BYTES;
        const float* wk = Wrow + it * 32;
        const float* ak = Arow + it * 32;
        #pragma unroll
        for (int i = 0; i < 4; i++) cp_async16(wbuf + dstOff[i], wk + srcOff[i]);
        #pragma unroll
        for (int i = 0; i < 4; i++) cp_async16(abuf + dstOff[i], ak + srcOff[i]);
    };

    float acc[4][4][4];
    #pragma unroll
    for (int i = 0; i < 4; i++)
        #pragma unroll
        for (int j = 0; j < 4; j++)
            #pragma unroll
            for (int e = 0; e < 4; e++) acc[i][j][e] = 0.f;

    // prologue: stages 0..2
    #pragma unroll
    for (int p = 0; p < STG - 1; p++) { load_stage(p); cp_commit(); }

    for (int it = 0; it < KDIM / 32; ++it) {
        cp_wait<STG - 2>();
        __syncthreads();
        if (it + STG - 1 < KDIM / 32) load_stage(it + STG - 1);
        cp_commit();

        const uint32_t* wt = (const uint32_t*)(smem + (it % STG) * STAGE_BYTES);
        const uint32_t* at = (const uint32_t*)(smem + (it % STG) * STAGE_BYTES + TILE_BYTES);

        #pragma unroll
        for (int ks = 0; ks < 4; ks++) {
            const int col = ks * 8 + tg;
            uint32_t afr[4][4];
            #pragma unroll
            for (int i = 0; i < 4; i++) {
                const int r0 = nbase + i * 16 + g;
                afr[i][0] = wt[r0 * ROWSTRIDE + col];
                afr[i][1] = wt[(r0 + 8) * ROWSTRIDE + col];
                afr[i][2] = wt[r0 * ROWSTRIDE + col + 4];
                afr[i][3] = wt[(r0 + 8) * ROWSTRIDE + col + 4];
            }
            uint32_t bfr[4][2];
            #pragma unroll
            for (int j = 0; j < 4; j++) {
                const int r = mbase + j * 8 + g;
                bfr[j][0] = at[r * ROWSTRIDE + col];
                bfr[j][1] = at[r * ROWSTRIDE + col + 4];
            }
            #pragma unroll
            for (int i = 0; i < 4; i++)
                #pragma unroll
                for (int j = 0; j < 4; j++)
                    mma_tf32(acc[i][j], afr[i], bfr[j]);
        }
    }

    // epilogue: transpose Ct[n][m] -> C[m][n] via smem, add bias
    __syncthreads();
    float* cs = (float*)smem;        // [128 n][129 m]
    #pragma unroll
    for (int i = 0; i < 4; i++) {
        #pragma unroll
        for (int j = 0; j < 4; j++) {
            const int n = nbase + i * 16 + g;
            const int m = mbase + j * 8 + tg * 2;
            cs[n * 129 + m]           = acc[i][j][0];
            cs[n * 129 + m + 1]       = acc[i][j][1];
            cs[(n + 8) * 129 + m]     = acc[i][j][2];
            cs[(n + 8) * 129 + m + 1] = acc[i][j][3];
        }
    }
    __syncthreads();

    const int m = tid >> 1;
    const int nh = tid & 1;
    const float* brow = bias + ntile * 128 + nh * 64;
    float* Crow = C + (size_t)(mtile * 128 + m) * NDIM + ntile * 128 + nh * 64;
    #pragma unroll
    for (int q = 0; q < 16; q++) {
        float4 v;
        v.x = cs[(nh * 64 + q * 4 + 0) * 129 + m] + brow[q * 4 + 0];
        v.y = cs[(nh * 64 + q * 4 + 1) * 129 + m] + brow[q * 4 + 1];
        v.z = cs[(nh * 64 + q * 4 + 2) * 129 + m] + brow[q * 4 + 2];
        v.w = cs[(nh * 64 + q * 4 + 3) * 129 + m] + brow[q * 4 + 3];
        *(float4*)(Crow + q * 4) = v;
    }
    (void)Mrows;
}

// ---------------------------------------------------------------------------
// img -> tf32-rounded copy
// ---------------------------------------------------------------------------
__global__ __launch_bounds__(256)
void cvt_img(const float* __restrict__ in, float* __restrict__ out)
{
    const int i = blockIdx.x * 256 + threadIdx.x;
    float4 v = ((const float4*)in)[i];
    v.x = tf32r(v.x); v.y = tf32r(v.y); v.z = tf32r(v.z); v.w = tf32r(v.w);
    ((float4*)out)[i] = v;
}

// W [K,N] -> WT [N,K], tf32-rounded. block (32,8), grid (32,32)
__global__ __launch_bounds__(256)
void transpose_cvt(const float* __restrict__ W, float* __restrict__ WT)
{
    __shared__ float t[32][33];
    const int x = blockIdx.x * 32 + threadIdx.x;
    const int y0 = blockIdx.y * 32 + threadIdx.y;
    #pragma unroll
    for (int i = 0; i < 32; i += 8)
        t[threadIdx.y + i][threadIdx.x] = W[(size_t)(y0 + i) * E_ + x];
    __syncthreads();
    const int x2 = blockIdx.y * 32 + threadIdx.x;
    const int y2 = blockIdx.x * 32 + threadIdx.y;
    #pragma unroll
    for (int i = 0; i < 32; i += 8)
        WT[(size_t)(y2 + i) * E_ + x2] = tf32r(t[threadIdx.x][threadIdx.y + i]);
}

// ---------------------------------------------------------------------------
// Tiny text projections
// ---------------------------------------------------------------------------
__global__ __launch_bounds__(256)
void small_proj(const float* __restrict__ text,
                const float* __restrict__ Wk, const float* __restrict__ bk,
                const float* __restrict__ Wv, const float* __restrict__ bv)
{
    const int b = blockIdx.y;
    const int n = blockIdx.x * 256 + threadIdx.x;
    __shared__ float ts[E_];
    for (int i = threadIdx.x; i < E_; i += 256) ts[i] = text[b * E_ + i];
    __syncthreads();
    float accK = 0.f, accV = 0.f;
    for (int k = 0; k < E_; k++) {
        const float t = ts[k];
        accK += t * Wk[(size_t)k * E_ + n];
        accV += t * Wv[(size_t)k * E_ + n];
    }
    g_kti[b * E_ + n] = accK + bk[n];
    g_vti[b * E_ + n] = accV + bv[n];
}

// ---------------------------------------------------------------------------
// Fused per-position attention over the HEADS axis;
// outputs rounded to tf32 (they feed the final tensor-core GEMM).
// ---------------------------------------------------------------------------
__global__ __launch_bounds__(256)
void attention_pos(const float* __restrict__ img, const float* __restrict__ text)
{
    const int n = blockIdx.x;
    const int b = blockIdx.y;
    const int tid = threadIdx.x;

    constexpr int PD = 65;
    __shared__ float xs[E_], ks[H_ * PD], vs[E_];
    __shared__ float txs[E_], ktis[H_ * PD], vtis[E_];
    __shared__ float att1[H_][H_], att2[H_][H_];

    const size_t rowOff = ((size_t)b * S_ + n) * E_;
    for (int i = tid; i < E_; i += 256) {
        const int l = i >> 6, j = i & 63;
        xs[i]  = img[rowOff + i];
        ks[l * PD + j]   = g_kit[rowOff + i];
        vs[i]  = g_vit[rowOff + i];
        txs[i] = text[b * E_ + i];
        ktis[l * PD + j] = g_kti[b * E_ + i];
        vtis[i] = g_vti[b * E_ + i];
    }
    __syncthreads();

    const int q = tid >> 4;
    const int l = tid & 15;
    float s1 = 0.f, s2 = 0.f;
    #pragma unroll 16
    for (int j = 0; j < D_; j++) {
        s1 += txs[q * 64 + j] * ks[l * PD + j];
        s2 += xs[q * 64 + j]  * ktis[l * PD + j];
    }
    s1 *= 0.125f; s2 *= 0.125f;

    float m1 = s1, m2 = s2;
    #pragma unroll
    for (int o = 8; o > 0; o >>= 1) {
        m1 = fmaxf(m1, __shfl_xor_sync(0xffffffffu, m1, o));
        m2 = fmaxf(m2, __shfl_xor_sync(0xffffffffu, m2, o));
    }
    float e1 = expf(s1 - m1), e2 = expf(s2 - m2);
    float z1 = e1, z2 = e2;
    #pragma unroll
    for (int o = 8; o > 0; o >>= 1) {
        z1 += __shfl_xor_sync(0xffffffffu, z1, o);
        z2 += __shfl_xor_sync(0xffffffffu, z2, o);
    }
    att1[q][l] = e1 / z1;
    att2[q][l] = e2 / z2;
    __syncthreads();

    float* cat_img  = g_cat + (((size_t)b * 2 * S_) + n) * E_;
    float* cat_text = g_cat + (((size_t)b * 2 * S_) + S_ + n) * E_;
    #pragma unroll
    for (int rep = 0; rep < 4; rep++) {
        const int idx = rep * 256 + tid;
        const int qq = idx >> 6, d = idx & 63;
        float o1 = 0.f, o2 = 0.f;
        #pragma unroll
        for (int ll = 0; ll < H_; ll++) {
            o1 += att1[qq][ll] * vs[ll * 64 + d];
            o2 += att2[qq][ll] * vtis[ll * 64 + d];
        }
        cat_img[idx]  = tf32r(o1);
        cat_text[idx] = tf32r(o2);
    }
}

// ---------------------------------------------------------------------------
extern "C" void kernel_launch(void* const* d_in, const int* in_sizes, int n_in,
                              void* d_out, int out_size)
{
    const float* img   = (const float*)d_in[0];
    const float* text  = (const float*)d_in[1];
    const float* W_kit = (const float*)d_in[2];
    const float* b_kit = (const float*)d_in[3];
    const float* W_vit = (const float*)d_in[4];
    const float* b_vit = (const float*)d_in[5];
    const float* W_kti = (const float*)d_in[6];
    const float* b_kti = (const float*)d_in[7];
    const float* W_vti = (const float*)d_in[8];
    const float* b_vti = (const float*)d_in[9];
    const float* W_out = (const float*)d_in[10];
    const float* b_out = (const float*)d_in[11];
    float* out = (float*)d_out;

    float *a32, *kit, *vit, *cat, *wkT, *wvT, *woT;
    cudaGetSymbolAddress((void**)&a32, g_a32);
    cudaGetSymbolAddress((void**)&kit, g_kit);
    cudaGetSymbolAddress((void**)&vit, g_vit);
    cudaGetSymbolAddress((void**)&cat, g_cat);
    cudaGetSymbolAddress((void**)&wkT, g_wkT);
    cudaGetSymbolAddress((void**)&wvT, g_wvT);
    cudaGetSymbolAddress((void**)&woT, g_woT);

    cudaFuncSetAttribute(gemm_tc, cudaFuncAttributeMaxDynamicSharedMemorySize, GEMM_SMEM);

    // operand preparation
    cvt_img<<<(M1 * E_ / 4) / 256, 256>>>(img, a32);
    transpose_cvt<<<dim3(32, 32), dim3(32, 8)>>>(W_kit, wkT);
    transpose_cvt<<<dim3(32, 32), dim3(32, 8)>>>(W_vit, wvT);
    transpose_cvt<<<dim3(32, 32), dim3(32, 8)>>>(W_out, woT);
    small_proj<<<dim3(E_ / 256, B_), 256>>>(text, W_kti, b_kti, W_vti, b_vti);

    // tensor-core tf32 GEMMs: k_it, v_it
    gemm_tc<<<dim3(8, M1 / 128), 256, GEMM_SMEM>>>(a32, wkT, b_kit, kit, M1);
    gemm_tc<<<dim3(8, M1 / 128), 256, GEMM_SMEM>>>(a32, wvT, b_vit, vit, M1);

    // fused attention -> cat (tf32-rounded)
    attention_pos<<<dim3(S_, B_), 256>>>(img, text);

    // final projection
    gemm_tc<<<dim3(8, M2 / 128), 256, GEMM_SMEM>>>(cat, woT, b_out, out, M2);
}

// round 4
// speedup vs baseline: 3.0548x; 1.1247x over previous
#include <cuda_runtime.h>
#include <cstdint>
#include <math.h>

// Problem constants
#define B_   8
#define S_   4096
#define E_   1024
#define H_   16
#define D_   64
#define M1   (B_ * S_)        // 32768
#define M2   (B_ * 2 * S_)    // 65536
#define KDIM 1024
#define NDIM 1024

// Scratch (device globals)
__device__ float g_a32[M1 * E_];    // img rounded to tf32
__device__ float g_kit[M1 * E_];
__device__ float g_vit[M1 * E_];
__device__ float g_kti[B_ * E_];
__device__ float g_vti[B_ * E_];
__device__ float g_cat[M2 * E_];    // concat, tf32-rounded
__device__ float g_wkT[E_ * E_];    // W^T (tf32-rounded), [N,K] K-major
__device__ float g_wvT[E_ * E_];
__device__ float g_woT[E_ * E_];

// ---------------------------------------------------------------------------
// helpers
// ---------------------------------------------------------------------------
__device__ __forceinline__ uint32_t smem_u32(const void* p) {
    uint32_t a;
    asm("{ .reg .u64 t; cvta.to.shared.u64 t, %1; cvt.u32.u64 %0, t; }" : "=r"(a) : "l"(p));
    return a;
}
__device__ __forceinline__ float tf32r(float x) {
    uint32_t u; asm("cvt.rna.tf32.f32 %0, %1;" : "=r"(u) : "f"(x));
    return __uint_as_float(u);
}
__device__ __forceinline__ void cp_async16(uint32_t dst, const void* src) {
    asm volatile("cp.async.cg.shared.global [%0], [%1], 16;" :: "r"(dst), "l"(src) : "memory");
}
__device__ __forceinline__ void cp_commit() {
    asm volatile("cp.async.commit_group;" ::: "memory");
}
template <int N> __device__ __forceinline__ void cp_wait() {
    asm volatile("cp.async.wait_group %0;" :: "n"(N) : "memory");
}
__device__ __forceinline__ void mma_tf32(float* d, const uint32_t* a, const uint32_t* b) {
    asm volatile(
        "mma.sync.aligned.m16n8k8.row.col.f32.tf32.tf32.f32 "
        "{%0,%1,%2,%3}, {%4,%5,%6,%7}, {%8,%9}, {%0,%1,%2,%3};"
        : "+f"(d[0]), "+f"(d[1]), "+f"(d[2]), "+f"(d[3])
        : "r"(a[0]), "r"(a[1]), "r"(a[2]), "r"(a[3]), "r"(b[0]), "r"(b[1]));
}

// ---------------------------------------------------------------------------
// Tensor-core tf32 GEMM:  C[M,1024] = A[M,1024] @ Wt[1024,1024]^T + bias
// Block tile 128(m) x 128(n), K in 32-wide stages, 3-stage cp.async pipeline,
// 2 CTAs per SM for latency hiding. 8 warps, warp tile n64 x m32.
// ---------------------------------------------------------------------------
#define STG 3
#define ROWSTRIDE 36                       // floats per smem row (conflict-free)
#define TILE_BYTES (128 * ROWSTRIDE * 4)   // 18432
#define STAGE_BYTES (2 * TILE_BYTES)       // Wt tile + act tile
#define GEMM_SMEM (STG * STAGE_BYTES)      // 110592

__global__ __launch_bounds__(256, 2)
void gemm_tc(const float* __restrict__ A, const float* __restrict__ Wt,
             const float* __restrict__ bias, float* __restrict__ C, int Mrows)
{
    extern __shared__ char smem[];
    const uint32_t sbase = smem_u32(smem);
    const int tid = threadIdx.x;
    const int wid = tid >> 5, lane = tid & 31;
    const int g = lane >> 2, tg = lane & 3;

    const int ntile = blockIdx.x, mtile = blockIdx.y;
    const int nbase = (wid >> 2) * 64;   // warp n-offset (0 or 64)
    const int mbase = (wid & 3) * 32;    // warp m-offset (0,32,64,96)

    const float* Wrow = Wt + (size_t)ntile * 128 * KDIM;
    const float* Arow = A + (size_t)mtile * 128 * KDIM;

    int srcOff[4];
    uint32_t dstOff[4];
    #pragma unroll
    for (int i = 0; i < 4; i++) {
        int c = tid + i * 256;
        int r = c >> 3, c4 = c & 7;
        srcOff[i] = r * KDIM + c4 * 4;
        dstOff[i] = (uint32_t)(r * (ROWSTRIDE * 4) + c4 * 16);
    }

    auto load_stage = [&](int it) {
        const uint32_t wbuf = sbase + (it % STG) * STAGE_BYTES;
        const uint32_t abuf = wbuf + TILE_BYTES;
        const float* wk = Wrow + it * 32;
        const float* ak = Arow + it * 32;
        #pragma unroll
        for (int i = 0; i < 4; i++) cp_async16(wbuf + dstOff[i], wk + srcOff[i]);
        #pragma unroll
        for (int i = 0; i < 4; i++) cp_async16(abuf + dstOff[i], ak + srcOff[i]);
    };

    float acc[4][4][4];
    #pragma unroll
    for (int i = 0; i < 4; i++)
        #pragma unroll
        for (int j = 0; j < 4; j++)
            #pragma unroll
            for (int e = 0; e < 4; e++) acc[i][j][e] = 0.f;

    #pragma unroll
    for (int p = 0; p < STG - 1; p++) { load_stage(p); cp_commit(); }

    for (int it = 0; it < KDIM / 32; ++it) {
        cp_wait<STG - 2>();
        __syncthreads();
        if (it + STG - 1 < KDIM / 32) load_stage(it + STG - 1);
        cp_commit();

        const uint32_t* wt = (const uint32_t*)(smem + (it % STG) * STAGE_BYTES);
        const uint32_t* at = (const uint32_t*)(smem + (it % STG) * STAGE_BYTES + TILE_BYTES);

        #pragma unroll
        for (int ks = 0; ks < 4; ks++) {
            const int col = ks * 8 + tg;
            uint32_t afr[4][4];
            #pragma unroll
            for (int i = 0; i < 4; i++) {
                const int r0 = nbase + i * 16 + g;
                afr[i][0] = wt[r0 * ROWSTRIDE + col];
                afr[i][1] = wt[(r0 + 8) * ROWSTRIDE + col];
                afr[i][2] = wt[r0 * ROWSTRIDE + col + 4];
                afr[i][3] = wt[(r0 + 8) * ROWSTRIDE + col + 4];
            }
            uint32_t bfr[4][2];
            #pragma unroll
            for (int j = 0; j < 4; j++) {
                const int r = mbase + j * 8 + g;
                bfr[j][0] = at[r * ROWSTRIDE + col];
                bfr[j][1] = at[r * ROWSTRIDE + col + 4];
            }
            #pragma unroll
            for (int i = 0; i < 4; i++)
                #pragma unroll
                for (int j = 0; j < 4; j++)
                    mma_tf32(acc[i][j], afr[i], bfr[j]);
        }
    }

    // epilogue: transpose Ct[n][m] -> C[m][n] via smem, add bias
    __syncthreads();
    float* cs = (float*)smem;        // [128 n][129 m]
    #pragma unroll
    for (int i = 0; i < 4; i++) {
        #pragma unroll
        for (int j = 0; j < 4; j++) {
            const int n = nbase + i * 16 + g;
            const int m = mbase + j * 8 + tg * 2;
            cs[n * 129 + m]           = acc[i][j][0];
            cs[n * 129 + m + 1]       = acc[i][j][1];
            cs[(n + 8) * 129 + m]     = acc[i][j][2];
            cs[(n + 8) * 129 + m + 1] = acc[i][j][3];
        }
    }
    __syncthreads();

    const int m = tid >> 1;
    const int nh = tid & 1;
    const float* brow = bias + ntile * 128 + nh * 64;
    float* Crow = C + (size_t)(mtile * 128 + m) * NDIM + ntile * 128 + nh * 64;
    #pragma unroll
    for (int q = 0; q < 16; q++) {
        float4 v;
        v.x = cs[(nh * 64 + q * 4 + 0) * 129 + m] + brow[q * 4 + 0];
        v.y = cs[(nh * 64 + q * 4 + 1) * 129 + m] + brow[q * 4 + 1];
        v.z = cs[(nh * 64 + q * 4 + 2) * 129 + m] + brow[q * 4 + 2];
        v.w = cs[(nh * 64 + q * 4 + 3) * 129 + m] + brow[q * 4 + 3];
        *(float4*)(Crow + q * 4) = v;
    }
    (void)Mrows;
}

// ---------------------------------------------------------------------------
// img -> tf32-rounded copy
// ---------------------------------------------------------------------------
__global__ __launch_bounds__(256)
void cvt_img(const float* __restrict__ in, float* __restrict__ out)
{
    const int i = blockIdx.x * 256 + threadIdx.x;
    float4 v = ((const float4*)in)[i];
    v.x = tf32r(v.x); v.y = tf32r(v.y); v.z = tf32r(v.z); v.w = tf32r(v.w);
    ((float4*)out)[i] = v;
}

// W [K,N] -> WT [N,K], tf32-rounded. block (32,8), grid (32,32)
__global__ __launch_bounds__(256)
void transpose_cvt(const float* __restrict__ W, float* __restrict__ WT)
{
    __shared__ float t[32][33];
    const int x = blockIdx.x * 32 + threadIdx.x;
    const int y0 = blockIdx.y * 32 + threadIdx.y;
    #pragma unroll
    for (int i = 0; i < 32; i += 8)
        t[threadIdx.y + i][threadIdx.x] = W[(size_t)(y0 + i) * E_ + x];
    __syncthreads();
    const int x2 = blockIdx.y * 32 + threadIdx.x;
    const int y2 = blockIdx.x * 32 + threadIdx.y;
    #pragma unroll
    for (int i = 0; i < 32; i += 8)
        WT[(size_t)(y2 + i) * E_ + x2] = tf32r(t[threadIdx.x][threadIdx.y + i]);
}

// ---------------------------------------------------------------------------
// Tiny text projections
// ---------------------------------------------------------------------------
__global__ __launch_bounds__(256)
void small_proj(const float* __restrict__ text,
                const float* __restrict__ Wk, const float* __restrict__ bk,
                const float* __restrict__ Wv, const float* __restrict__ bv)
{
    const int b = blockIdx.y;
    const int n = blockIdx.x * 256 + threadIdx.x;
    __shared__ float ts[E_];
    for (int i = threadIdx.x; i < E_; i += 256) ts[i] = text[b * E_ + i];
    __syncthreads();
    float accK = 0.f, accV = 0.f;
    for (int k = 0; k < E_; k++) {
        const float t = ts[k];
        accK += t * Wk[(size_t)k * E_ + n];
        accV += t * Wv[(size_t)k * E_ + n];
    }
    g_kti[b * E_ + n] = accK + bk[n];
    g_vti[b * E_ + n] = accV + bv[n];
}

// ---------------------------------------------------------------------------
// Fused per-position attention over the HEADS axis, 2 positions per block.
// float4 everywhere; outputs tf32-rounded for the final tensor-core GEMM.
// ---------------------------------------------------------------------------
#define NPOS 2
#define PD 65

__global__ __launch_bounds__(256)
void attention_pos(const float* __restrict__ img, const float* __restrict__ text)
{
    const int n0 = blockIdx.x * NPOS;
    const int b = blockIdx.y;
    const int tid = threadIdx.x;

    __shared__ float4 xs4[NPOS][256], vs4[NPOS][256], txs4[256], vtis4[256];
    __shared__ float ks[NPOS][H_ * PD], ktis[H_ * PD];
    __shared__ float att1[NPOS][H_][H_], att2[NPOS][H_][H_];

    const size_t r0 = (size_t)b * S_ + n0;
    {
        const int e = tid * 4, l = e >> 6, j = e & 63;
        #pragma unroll
        for (int p = 0; p < NPOS; p++) {
            xs4[p][tid] = ((const float4*)img)[(r0 + p) * 256 + tid];
            vs4[p][tid] = ((const float4*)g_vit)[(r0 + p) * 256 + tid];
            float4 vk = ((const float4*)g_kit)[(r0 + p) * 256 + tid];
            float* kp = &ks[p][l * PD + j];
            kp[0] = vk.x; kp[1] = vk.y; kp[2] = vk.z; kp[3] = vk.w;
        }
        txs4[tid]  = ((const float4*)text)[b * 256 + tid];
        vtis4[tid] = ((const float4*)g_vti)[b * 256 + tid];
        float4 vkt = ((const float4*)g_kti)[b * 256 + tid];
        float* kp = &ktis[l * PD + j];
        kp[0] = vkt.x; kp[1] = vkt.y; kp[2] = vkt.z; kp[3] = vkt.w;
    }
    __syncthreads();

    // scores: thread t -> (q = t>>4, l = t&15), for both positions
    const int q = tid >> 4;
    const int l = tid & 15;
    const float* txq = (const float*)txs4 + q * 64;
    const float* x0q = (const float*)xs4[0] + q * 64;
    const float* x1q = (const float*)xs4[1] + q * 64;

    float s1a = 0.f, s1b = 0.f, s2a = 0.f, s2b = 0.f;
    #pragma unroll
    for (int j = 0; j < D_; j++) {
        const float tv  = txq[j];
        const float ktv = ktis[l * PD + j];
        s1a += tv * ks[0][l * PD + j];
        s1b += tv * ks[1][l * PD + j];
        s2a += x0q[j] * ktv;
        s2b += x1q[j] * ktv;
    }
    s1a *= 0.125f; s1b *= 0.125f; s2a *= 0.125f; s2b *= 0.125f;

    float m1a = s1a, m1b = s1b, m2a = s2a, m2b = s2b;
    #pragma unroll
    for (int o = 8; o > 0; o >>= 1) {
        m1a = fmaxf(m1a, __shfl_xor_sync(0xffffffffu, m1a, o));
        m1b = fmaxf(m1b, __shfl_xor_sync(0xffffffffu, m1b, o));
        m2a = fmaxf(m2a, __shfl_xor_sync(0xffffffffu, m2a, o));
        m2b = fmaxf(m2b, __shfl_xor_sync(0xffffffffu, m2b, o));
    }
    float e1a = expf(s1a - m1a), e1b = expf(s1b - m1b);
    float e2a = expf(s2a - m2a), e2b = expf(s2b - m2b);
    float z1a = e1a, z1b = e1b, z2a = e2a, z2b = e2b;
    #pragma unroll
    for (int o = 8; o > 0; o >>= 1) {
        z1a += __shfl_xor_sync(0xffffffffu, z1a, o);
        z1b += __shfl_xor_sync(0xffffffffu, z1b, o);
        z2a += __shfl_xor_sync(0xffffffffu, z2a, o);
        z2b += __shfl_xor_sync(0xffffffffu, z2b, o);
    }
    att1[0][q][l] = e1a / z1a;  att1[1][q][l] = e1b / z1b;
    att2[0][q][l] = e2a / z2a;  att2[1][q][l] = e2b / z2b;
    __syncthreads();

    // outputs: thread owns 4 consecutive d of one (p-independent) (qq,d) slot
    const int qq = tid >> 4;
    const int dv = tid & 15;              // float4 index within head (d = dv*4)
    float4* cat4 = (float4*)g_cat;
    const size_t baseImg  = ((size_t)b * 2 * S_ + n0) * 256;
    const size_t baseText = ((size_t)b * 2 * S_ + S_ + n0) * 256;

    #pragma unroll
    for (int p = 0; p < NPOS; p++) {
        float4 o1 = make_float4(0.f, 0.f, 0.f, 0.f);
        float4 o2 = make_float4(0.f, 0.f, 0.f, 0.f);
        #pragma unroll
        for (int ll = 0; ll < H_; ll++) {
            const float a1 = att1[p][qq][ll];
            const float a2 = att2[p][qq][ll];
            const float4 vv = vs4[p][ll * 16 + dv];
            const float4 vt = vtis4[ll * 16 + dv];
            o1.x += a1 * vv.x; o1.y += a1 * vv.y; o1.z += a1 * vv.z; o1.w += a1 * vv.w;
            o2.x += a2 * vt.x; o2.y += a2 * vt.y; o2.z += a2 * vt.z; o2.w += a2 * vt.w;
        }
        o1.x = tf32r(o1.x); o1.y = tf32r(o1.y); o1.z = tf32r(o1.z); o1.w = tf32r(o1.w);
        o2.x = tf32r(o2.x); o2.y = tf32r(o2.y); o2.z = tf32r(o2.z); o2.w = tf32r(o2.w);
        cat4[baseImg + (size_t)p * 256 + tid]  = o1;
        cat4[baseText + (size_t)p * 256 + tid] = o2;
    }
}

// ---------------------------------------------------------------------------
extern "C" void kernel_launch(void* const* d_in, const int* in_sizes, int n_in,
                              void* d_out, int out_size)
{
    const float* img   = (const float*)d_in[0];
    const float* text  = (const float*)d_in[1];
    const float* W_kit = (const float*)d_in[2];
    const float* b_kit = (const float*)d_in[3];
    const float* W_vit = (const float*)d_in[4];
    const float* b_vit = (const float*)d_in[5];
    const float* W_kti = (const float*)d_in[6];
    const float* b_kti = (const float*)d_in[7];
    const float* W_vti = (const float*)d_in[8];
    const float* b_vti = (const float*)d_in[9];
    const float* W_out = (const float*)d_in[10];
    const float* b_out = (const float*)d_in[11];
    float* out = (float*)d_out;

    float *a32, *kit, *vit, *cat, *wkT, *wvT, *woT;
    cudaGetSymbolAddress((void**)&a32, g_a32);
    cudaGetSymbolAddress((void**)&kit, g_kit);
    cudaGetSymbolAddress((void**)&vit, g_vit);
    cudaGetSymbolAddress((void**)&cat, g_cat);
    cudaGetSymbolAddress((void**)&wkT, g_wkT);
    cudaGetSymbolAddress((void**)&wvT, g_wvT);
    cudaGetSymbolAddress((void**)&woT, g_woT);

    cudaFuncSetAttribute(gemm_tc, cudaFuncAttributeMaxDynamicSharedMemorySize, GEMM_SMEM);

    // operand preparation
    cvt_img<<<(M1 * E_ / 4) / 256, 256>>>(img, a32);
    transpose_cvt<<<dim3(32, 32), dim3(32, 8)>>>(W_kit, wkT);
    transpose_cvt<<<dim3(32, 32), dim3(32, 8)>>>(W_vit, wvT);
    transpose_cvt<<<dim3(32, 32), dim3(32, 8)>>>(W_out, woT);
    small_proj<<<dim3(E_ / 256, B_), 256>>>(text, W_kti, b_kti, W_vti, b_vti);

    // tensor-core tf32 GEMMs: k_it, v_it
    gemm_tc<<<dim3(8, M1 / 128), 256, GEMM_SMEM>>>(a32, wkT, b_kit, kit, M1);
    gemm_tc<<<dim3(8, M1 / 128), 256, GEMM_SMEM>>>(a32, wvT, b_vit, vit, M1);

    // fused attention -> cat (tf32-rounded)
    attention_pos<<<dim3(S_ / NPOS, B_), 256>>>(img, text);

    // final projection
    gemm_tc<<<dim3(8, M2 / 128), 256, GEMM_SMEM>>>(cat, woT, b_out, out, M2);
}

// round 5
// speedup vs baseline: 3.5093x; 1.1488x over previous
#include <cuda_runtime.h>
#include <cstdint>
#include <math.h>

// Problem constants
#define B_   8
#define S_   4096
#define E_   1024
#define H_   16
#define D_   64
#define M1   (B_ * S_)        // 32768
#define M2   (B_ * 2 * S_)    // 65536
#define NDIM 1024

// Scratch (device globals)
__device__ float g_a32[M1 * E_];    // img rounded to tf32
__device__ float g_kit[M1 * E_];
__device__ float g_vit[M1 * E_];
__device__ float g_kti[B_ * E_];
__device__ float g_vti[B_ * E_];
__device__ float g_cat[M1 * E_];    // img_out only (tf32-rounded)
__device__ float g_att2[M1 * 256];  // text attention weights (tf32)
__device__ float g_Pt[B_ * NDIM * 256]; // P^T per batch: [b][n][(q,l)] tf32
__device__ float g_wkT[E_ * E_];    // W^T (tf32-rounded), [N,K] K-major
__device__ float g_wvT[E_ * E_];
__device__ float g_woT[E_ * E_];

// ---------------------------------------------------------------------------
// helpers
// ---------------------------------------------------------------------------
__device__ __forceinline__ uint32_t smem_u32(const void* p) {
    uint32_t a;
    asm("{ .reg .u64 t; cvta.to.shared.u64 t, %1; cvt.u32.u64 %0, t; }" : "=r"(a) : "l"(p));
    return a;
}
__device__ __forceinline__ float tf32r(float x) {
    uint32_t u; asm("cvt.rna.tf32.f32 %0, %1;" : "=r"(u) : "f"(x));
    return __uint_as_float(u);
}
__device__ __forceinline__ void cp_async16(uint32_t dst, const void* src) {
    asm volatile("cp.async.cg.shared.global [%0], [%1], 16;" :: "r"(dst), "l"(src) : "memory");
}
__device__ __forceinline__ void cp_commit() {
    asm volatile("cp.async.commit_group;" ::: "memory");
}
template <int N> __device__ __forceinline__ void cp_wait() {
    asm volatile("cp.async.wait_group %0;" :: "n"(N) : "memory");
}
__device__ __forceinline__ void mma_tf32(float* d, const uint32_t* a, const uint32_t* b) {
    asm volatile(
        "mma.sync.aligned.m16n8k8.row.col.f32.tf32.tf32.f32 "
        "{%0,%1,%2,%3}, {%4,%5,%6,%7}, {%8,%9}, {%0,%1,%2,%3};"
        : "+f"(d[0]), "+f"(d[1]), "+f"(d[2]), "+f"(d[3])
        : "r"(a[0]), "r"(a[1]), "r"(a[2]), "r"(a[3]), "r"(b[0]), "r"(b[1]));
}

// ---------------------------------------------------------------------------
// Tensor-core tf32 GEMM (generalized):
//   C_rows = A[M,Kd] @ Wt_batch[1024,Kd]^T + bias
// Output row for (mtile,m): batch*outBStride + outOff + (mtile%mtPerB)*128 + m
// Wt pointer per batch: Wt + batch*wtBStride.   batch = mtile / mtPerB.
// Block tile 128x128, 32-wide K stages, 3-stage cp.async pipeline, 2 CTAs/SM.
// ---------------------------------------------------------------------------
#define STG 3
#define ROWSTRIDE 36
#define TILE_BYTES (128 * ROWSTRIDE * 4)
#define STAGE_BYTES (2 * TILE_BYTES)
#define GEMM_SMEM (STG * STAGE_BYTES)      // 110592

__global__ __launch_bounds__(256, 2)
void gemm_tc(const float* __restrict__ A, const float* __restrict__ Wt,
             const float* __restrict__ bias, float* __restrict__ C,
             int Kd, int mtPerB, int outBStride, int outOff, int wtBStride)
{
    extern __shared__ char smem[];
    const uint32_t sbase = smem_u32(smem);
    const int tid = threadIdx.x;
    const int wid = tid >> 5, lane = tid & 31;
    const int g = lane >> 2, tg = lane & 3;

    const int ntile = blockIdx.x, mtile = blockIdx.y;
    const int batch = mtile / mtPerB;
    const int mloc  = mtile % mtPerB;
    const int nbase = (wid >> 2) * 64;
    const int mbase = (wid & 3) * 32;

    const float* Wrow = Wt + (size_t)batch * wtBStride + (size_t)ntile * 128 * Kd;
    const float* Arow = A + (size_t)mtile * 128 * Kd;

    int srcOff[4];
    uint32_t dstOff[4];
    #pragma unroll
    for (int i = 0; i < 4; i++) {
        int c = tid + i * 256;
        int r = c >> 3, c4 = c & 7;
        srcOff[i] = r * Kd + c4 * 4;
        dstOff[i] = (uint32_t)(r * (ROWSTRIDE * 4) + c4 * 16);
    }

    auto load_stage = [&](int it) {
        const uint32_t wbuf = sbase + (it % STG) * STAGE_BYTES;
        const uint32_t abuf = wbuf + TILE_BYTES;
        const float* wk = Wrow + it * 32;
        const float* ak = Arow + it * 32;
        #pragma unroll
        for (int i = 0; i < 4; i++) cp_async16(wbuf + dstOff[i], wk + srcOff[i]);
        #pragma unroll
        for (int i = 0; i < 4; i++) cp_async16(abuf + dstOff[i], ak + srcOff[i]);
    };

    float acc[4][4][4];
    #pragma unroll
    for (int i = 0; i < 4; i++)
        #pragma unroll
        for (int j = 0; j < 4; j++)
            #pragma unroll
            for (int e = 0; e < 4; e++) acc[i][j][e] = 0.f;

    #pragma unroll
    for (int p = 0; p < STG - 1; p++) { load_stage(p); cp_commit(); }

    const int NIT = Kd / 32;
    for (int it = 0; it < NIT; ++it) {
        cp_wait<STG - 2>();
        __syncthreads();
        if (it + STG - 1 < NIT) load_stage(it + STG - 1);
        cp_commit();

        const uint32_t* wt = (const uint32_t*)(smem + (it % STG) * STAGE_BYTES);
        const uint32_t* at = (const uint32_t*)(smem + (it % STG) * STAGE_BYTES + TILE_BYTES);

        #pragma unroll
        for (int ks = 0; ks < 4; ks++) {
            const int col = ks * 8 + tg;
            uint32_t afr[4][4];
            #pragma unroll
            for (int i = 0; i < 4; i++) {
                const int r0 = nbase + i * 16 + g;
                afr[i][0] = wt[r0 * ROWSTRIDE + col];
                afr[i][1] = wt[(r0 + 8) * ROWSTRIDE + col];
                afr[i][2] = wt[r0 * ROWSTRIDE + col + 4];
                afr[i][3] = wt[(r0 + 8) * ROWSTRIDE + col + 4];
            }
            uint32_t bfr[4][2];
            #pragma unroll
            for (int j = 0; j < 4; j++) {
                const int r = mbase + j * 8 + g;
                bfr[j][0] = at[r * ROWSTRIDE + col];
                bfr[j][1] = at[r * ROWSTRIDE + col + 4];
            }
            #pragma unroll
            for (int i = 0; i < 4; i++)
                #pragma unroll
                for (int j = 0; j < 4; j++)
                    mma_tf32(acc[i][j], afr[i], bfr[j]);
        }
    }

    // epilogue: transpose Ct[n][m] -> C[m][n] via smem, add bias
    __syncthreads();
    float* cs = (float*)smem;        // [128 n][129 m]
    #pragma unroll
    for (int i = 0; i < 4; i++) {
        #pragma unroll
        for (int j = 0; j < 4; j++) {
            const int n = nbase + i * 16 + g;
            const int m = mbase + j * 8 + tg * 2;
            cs[n * 129 + m]           = acc[i][j][0];
            cs[n * 129 + m + 1]       = acc[i][j][1];
            cs[(n + 8) * 129 + m]     = acc[i][j][2];
            cs[(n + 8) * 129 + m + 1] = acc[i][j][3];
        }
    }
    __syncthreads();

    const int m = tid >> 1;
    const int nh = tid & 1;
    const size_t outRow = (size_t)batch * outBStride + outOff + mloc * 128 + m;
    const float* brow = bias + ntile * 128 + nh * 64;
    float* Crow = C + outRow * NDIM + ntile * 128 + nh * 64;
    #pragma unroll
    for (int q = 0; q < 16; q++) {
        float4 v;
        v.x = cs[(nh * 64 + q * 4 + 0) * 129 + m] + brow[q * 4 + 0];
        v.y = cs[(nh * 64 + q * 4 + 1) * 129 + m] + brow[q * 4 + 1];
        v.z = cs[(nh * 64 + q * 4 + 2) * 129 + m] + brow[q * 4 + 2];
        v.w = cs[(nh * 64 + q * 4 + 3) * 129 + m] + brow[q * 4 + 3];
        *(float4*)(Crow + q * 4) = v;
    }
}

// ---------------------------------------------------------------------------
// img -> tf32-rounded copy
// ---------------------------------------------------------------------------
__global__ __launch_bounds__(256)
void cvt_img(const float* __restrict__ in, float* __restrict__ out)
{
    const int i = blockIdx.x * 256 + threadIdx.x;
    float4 v = ((const float4*)in)[i];
    v.x = tf32r(v.x); v.y = tf32r(v.y); v.z = tf32r(v.z); v.w = tf32r(v.w);
    ((float4*)out)[i] = v;
}

// W [K,N] -> WT [N,K], tf32-rounded.
__global__ __launch_bounds__(256)
void transpose_cvt(const float* __restrict__ W, float* __restrict__ WT)
{
    __shared__ float t[32][33];
    const int x = blockIdx.x * 32 + threadIdx.x;
    const int y0 = blockIdx.y * 32 + threadIdx.y;
    #pragma unroll
    for (int i = 0; i < 32; i += 8)
        t[threadIdx.y + i][threadIdx.x] = W[(size_t)(y0 + i) * E_ + x];
    __syncthreads();
    const int x2 = blockIdx.y * 32 + threadIdx.x;
    const int y2 = blockIdx.x * 32 + threadIdx.y;
    #pragma unroll
    for (int i = 0; i < 32; i += 8)
        WT[(size_t)(y2 + i) * E_ + x2] = tf32r(t[threadIdx.x][threadIdx.y + i]);
}

// ---------------------------------------------------------------------------
// Tiny text projections
// ---------------------------------------------------------------------------
__global__ __launch_bounds__(256)
void small_proj(const float* __restrict__ text,
                const float* __restrict__ Wk, const float* __restrict__ bk,
                const float* __restrict__ Wv, const float* __restrict__ bv)
{
    const int b = blockIdx.y;
    const int n = blockIdx.x * 256 + threadIdx.x;
    __shared__ float ts[E_];
    for (int i = threadIdx.x; i < E_; i += 256) ts[i] = text[b * E_ + i];
    __syncthreads();
    float accK = 0.f, accV = 0.f;
    for (int k = 0; k < E_; k++) {
        const float t = ts[k];
        accK += t * Wk[(size_t)k * E_ + n];
        accV += t * Wv[(size_t)k * E_ + n];
    }
    g_kti[b * E_ + n] = accK + bk[n];
    g_vti[b * E_ + n] = accV + bv[n];
}

// ---------------------------------------------------------------------------
// Pt[b][n][(q*16+l)] = tf32( sum_d v_ti[b, l*64+d] * W_out[(q*64+d)*1024 + n] )
// grid (4, 256=(q,l)), 256 threads: thread = n within chunk, 8 batches in regs.
// ---------------------------------------------------------------------------
__global__ __launch_bounds__(256)
void compute_Pt(const float* __restrict__ W_out)
{
    const int n = blockIdx.x * 256 + threadIdx.x;
    const int ql = blockIdx.y;
    const int q = ql >> 4, l = ql & 15;

    __shared__ float vt[B_][D_];
    for (int i = threadIdx.x; i < B_ * D_; i += 256)
        vt[i / D_][i % D_] = g_vti[(i / D_) * E_ + l * 64 + (i % D_)];
    __syncthreads();

    float acc[B_];
    #pragma unroll
    for (int b = 0; b < B_; b++) acc[b] = 0.f;
    #pragma unroll 8
    for (int d = 0; d < D_; d++) {
        const float w = W_out[(size_t)(q * 64 + d) * NDIM + n];
        #pragma unroll
        for (int b = 0; b < B_; b++) acc[b] += w * vt[b][d];
    }
    #pragma unroll
    for (int b = 0; b < B_; b++)
        g_Pt[(size_t)b * (NDIM * 256) + (size_t)n * 256 + ql] = tf32r(acc[b]);
}

// ---------------------------------------------------------------------------
// Fused per-position attention, 2 positions/block.
// Writes img_out (tf32) to g_cat and att2 weights (tf32) to g_att2.
// ---------------------------------------------------------------------------
#define NPOS 2
#define PD 65

__global__ __launch_bounds__(256)
void attention_pos(const float* __restrict__ img, const float* __restrict__ text)
{
    const int n0 = blockIdx.x * NPOS;
    const int b = blockIdx.y;
    const int tid = threadIdx.x;

    __shared__ float4 xs4[NPOS][256], vs4[NPOS][256], txs4[256];
    __shared__ float ks[NPOS][H_ * PD], ktis[H_ * PD];
    __shared__ float att1[NPOS][H_][H_];

    const size_t r0 = (size_t)b * S_ + n0;
    {
        const int e = tid * 4, l = e >> 6, j = e & 63;
        #pragma unroll
        for (int p = 0; p < NPOS; p++) {
            xs4[p][tid] = ((const float4*)img)[(r0 + p) * 256 + tid];
            vs4[p][tid] = ((const float4*)g_vit)[(r0 + p) * 256 + tid];
            float4 vk = ((const float4*)g_kit)[(r0 + p) * 256 + tid];
            float* kp = &ks[p][l * PD + j];
            kp[0] = vk.x; kp[1] = vk.y; kp[2] = vk.z; kp[3] = vk.w;
        }
        txs4[tid] = ((const float4*)text)[b * 256 + tid];
        float4 vkt = ((const float4*)g_kti)[b * 256 + tid];
        float* kp = &ktis[l * PD + j];
        kp[0] = vkt.x; kp[1] = vkt.y; kp[2] = vkt.z; kp[3] = vkt.w;
    }
    __syncthreads();

    const int q = tid >> 4;
    const int l = tid & 15;
    const float* txq = (const float*)txs4 + q * 64;
    const float* x0q = (const float*)xs4[0] + q * 64;
    const float* x1q = (const float*)xs4[1] + q * 64;

    float s1a = 0.f, s1b = 0.f, s2a = 0.f, s2b = 0.f;
    #pragma unroll
    for (int j = 0; j < D_; j++) {
        const float tv  = txq[j];
        const float ktv = ktis[l * PD + j];
        s1a += tv * ks[0][l * PD + j];
        s1b += tv * ks[1][l * PD + j];
        s2a += x0q[j] * ktv;
        s2b += x1q[j] * ktv;
    }
    s1a *= 0.125f; s1b *= 0.125f; s2a *= 0.125f; s2b *= 0.125f;

    float m1a = s1a, m1b = s1b, m2a = s2a, m2b = s2b;
    #pragma unroll
    for (int o = 8; o > 0; o >>= 1) {
        m1a = fmaxf(m1a, __shfl_xor_sync(0xffffffffu, m1a, o));
        m1b = fmaxf(m1b, __shfl_xor_sync(0xffffffffu, m1b, o));
        m2a = fmaxf(m2a, __shfl_xor_sync(0xffffffffu, m2a, o));
        m2b = fmaxf(m2b, __shfl_xor_sync(0xffffffffu, m2b, o));
    }
    float e1a = expf(s1a - m1a), e1b = expf(s1b - m1b);
    float e2a = expf(s2a - m2a), e2b = expf(s2b - m2b);
    float z1a = e1a, z1b = e1b, z2a = e2a, z2b = e2b;
    #pragma unroll
    for (int o = 8; o > 0; o >>= 1) {
        z1a += __shfl_xor_sync(0xffffffffu, z1a, o);
        z1b += __shfl_xor_sync(0xffffffffu, z1b, o);
        z2a += __shfl_xor_sync(0xffffffffu, z2a, o);
        z2b += __shfl_xor_sync(0xffffffffu, z2b, o);
    }
    att1[0][q][l] = e1a / z1a;  att1[1][q][l] = e1b / z1b;
    // text attention weights -> g_att2 (A operand of the K=256 GEMM), coalesced
    g_att2[(r0 + 0) * 256 + tid] = tf32r(e2a / z2a);
    g_att2[(r0 + 1) * 256 + tid] = tf32r(e2b / z2b);
    __syncthreads();

    // img outputs: thread owns float4 slot (qq, dv)
    const int qq = tid >> 4;
    const int dv = tid & 15;
    float4* cat4 = (float4*)g_cat;
    #pragma unroll
    for (int p = 0; p < NPOS; p++) {
        float4 o1 = make_float4(0.f, 0.f, 0.f, 0.f);
        #pragma unroll
        for (int ll = 0; ll < H_; ll++) {
            const float a1 = att1[p][qq][ll];
            const float4 vv = vs4[p][ll * 16 + dv];
            o1.x += a1 * vv.x; o1.y += a1 * vv.y; o1.z += a1 * vv.z; o1.w += a1 * vv.w;
        }
        o1.x = tf32r(o1.x); o1.y = tf32r(o1.y); o1.z = tf32r(o1.z); o1.w = tf32r(o1.w);
        cat4[(r0 + p) * 256 + tid] = o1;
    }
}

// ---------------------------------------------------------------------------
extern "C" void kernel_launch(void* const* d_in, const int* in_sizes, int n_in,
                              void* d_out, int out_size)
{
    const float* img   = (const float*)d_in[0];
    const float* text  = (const float*)d_in[1];
    const float* W_kit = (const float*)d_in[2];
    const float* b_kit = (const float*)d_in[3];
    const float* W_vit = (const float*)d_in[4];
    const float* b_vit = (const float*)d_in[5];
    const float* W_kti = (const float*)d_in[6];
    const float* b_kti = (const float*)d_in[7];
    const float* W_vti = (const float*)d_in[8];
    const float* b_vti = (const float*)d_in[9];
    const float* W_out = (const float*)d_in[10];
    const float* b_out = (const float*)d_in[11];
    float* out = (float*)d_out;

    float *a32, *kit, *vit, *cat, *att2, *Pt, *wkT, *wvT, *woT;
    cudaGetSymbolAddress((void**)&a32, g_a32);
    cudaGetSymbolAddress((void**)&kit, g_kit);
    cudaGetSymbolAddress((void**)&vit, g_vit);
    cudaGetSymbolAddress((void**)&cat, g_cat);
    cudaGetSymbolAddress((void**)&att2, g_att2);
    cudaGetSymbolAddress((void**)&Pt, g_Pt);
    cudaGetSymbolAddress((void**)&wkT, g_wkT);
    cudaGetSymbolAddress((void**)&wvT, g_wvT);
    cudaGetSymbolAddress((void**)&woT, g_woT);

    cudaFuncSetAttribute(gemm_tc, cudaFuncAttributeMaxDynamicSharedMemorySize, GEMM_SMEM);

    // operand preparation
    cvt_img<<<(M1 * E_ / 4) / 256, 256>>>(img, a32);
    transpose_cvt<<<dim3(32, 32), dim3(32, 8)>>>(W_kit, wkT);
    transpose_cvt<<<dim3(32, 32), dim3(32, 8)>>>(W_vit, wvT);
    transpose_cvt<<<dim3(32, 32), dim3(32, 8)>>>(W_out, woT);
    small_proj<<<dim3(E_ / 256, B_), 256>>>(text, W_kti, b_kti, W_vti, b_vti);
    compute_Pt<<<dim3(4, 256), 256>>>(W_out);

    // tensor-core tf32 GEMMs: k_it, v_it  (plain scratch output)
    gemm_tc<<<dim3(8, M1 / 128), 256, GEMM_SMEM>>>(a32, wkT, b_kit, kit,
                                                   1024, 256, 0, 0, 0);
    gemm_tc<<<dim3(8, M1 / 128), 256, GEMM_SMEM>>>(a32, wvT, b_vit, vit,
                                                   1024, 256, 0, 0, 0);

    // fused attention -> img_out (g_cat) + att2 weights
    attention_pos<<<dim3(S_ / NPOS, B_), 256>>>(img, text);

    // final projection, img half: rows b*8192 + n
    gemm_tc<<<dim3(8, M1 / 128), 256, GEMM_SMEM>>>(cat, woT, b_out, out,
                                                   1024, 32, 8192, 0, 0);
    // final projection, text half (factored): K=256, rows b*8192 + 4096 + n
    gemm_tc<<<dim3(8, M1 / 128), 256, GEMM_SMEM>>>(att2, Pt, b_out, out,
                                                   256, 32, 8192, 4096, 256 * 1024);
}

// round 6
// speedup vs baseline: 3.7141x; 1.0584x over previous
#include <cuda_runtime.h>
#include <cstdint>
#include <math.h>

// Problem constants
#define B_   8
#define S_   4096
#define E_   1024
#define H_   16
#define D_   64
#define M1   (B_ * S_)        // 32768
#define NDIM 1024

// Scratch (device globals)
__device__ float g_a32[M1 * E_];    // img rounded to tf32
__device__ float g_kit[M1 * E_];
__device__ float g_vit[M1 * E_];
__device__ float g_kti[B_ * E_];
__device__ float g_vti[B_ * E_];
__device__ float g_cat[M1 * E_];    // img_out only (tf32-rounded)
__device__ float g_att2[M1 * 256];  // text attention weights (tf32)
__device__ float g_Pt[B_ * NDIM * 256]; // P^T per batch: [b][n][(q,l)] tf32
__device__ float g_wkT[E_ * E_];    // W^T (tf32-rounded), [N,K] K-major
__device__ float g_wvT[E_ * E_];
__device__ float g_woT[E_ * E_];

// ---------------------------------------------------------------------------
// helpers
// ---------------------------------------------------------------------------
__device__ __forceinline__ uint32_t smem_u32(const void* p) {
    uint32_t a;
    asm("{ .reg .u64 t; cvta.to.shared.u64 t, %1; cvt.u32.u64 %0, t; }" : "=r"(a) : "l"(p));
    return a;
}
__device__ __forceinline__ float tf32r(float x) {
    uint32_t u; asm("cvt.rna.tf32.f32 %0, %1;" : "=r"(u) : "f"(x));
    return __uint_as_float(u);
}
__device__ __forceinline__ void cp_async16(uint32_t dst, const void* src) {
    asm volatile("cp.async.cg.shared.global [%0], [%1], 16;" :: "r"(dst), "l"(src) : "memory");
}
__device__ __forceinline__ void cp_commit() {
    asm volatile("cp.async.commit_group;" ::: "memory");
}
template <int N> __device__ __forceinline__ void cp_wait() {
    asm volatile("cp.async.wait_group %0;" :: "n"(N) : "memory");
}
__device__ __forceinline__ void mma_tf32(float* d, const uint32_t* a, const uint32_t* b) {
    asm volatile(
        "mma.sync.aligned.m16n8k8.row.col.f32.tf32.tf32.f32 "
        "{%0,%1,%2,%3}, {%4,%5,%6,%7}, {%8,%9}, {%0,%1,%2,%3};"
        : "+f"(d[0]), "+f"(d[1]), "+f"(d[2]), "+f"(d[3])
        : "r"(a[0]), "r"(a[1]), "r"(a[2]), "r"(a[3]), "r"(b[0]), "r"(b[1]));
}

// ---------------------------------------------------------------------------
// Tensor-core tf32 GEMM (generalized, optional dual-weight split):
//   logical ntile' = blockIdx.x; if ntile' >= nsplit, use {Wt2,bias2,C2}.
//   C_rows = A[M,Kd] @ Wt[1024,Kd]^T + bias
// Output row: batch*outBStride + outOff + (mtile%mtPerB)*128 + m
// Wt per batch: Wt + batch*wtBStride.  batch = mtile / mtPerB.
// CTA tile 128x128, 4 warps (warp tile n64 x m64), 32-wide K stages,
// 3-stage cp.async pipeline, 2 CTAs/SM.
// ---------------------------------------------------------------------------
#define STG 3
#define ROWSTRIDE 36
#define TILE_BYTES (128 * ROWSTRIDE * 4)
#define STAGE_BYTES (2 * TILE_BYTES)
#define GEMM_SMEM (STG * STAGE_BYTES)      // 110592

__global__ __launch_bounds__(128, 2)
void gemm_tc(const float* __restrict__ A,
             const float* __restrict__ Wt,  const float* __restrict__ bias,  float* __restrict__ C,
             const float* __restrict__ Wt2, const float* __restrict__ bias2, float* __restrict__ C2,
             int Kd, int nsplit, int mtPerB, int outBStride, int outOff, int wtBStride)
{
    extern __shared__ char smem[];
    const uint32_t sbase = smem_u32(smem);
    const int tid = threadIdx.x;
    const int wid = tid >> 5, lane = tid & 31;
    const int g = lane >> 2, tg = lane & 3;

    int ntile = blockIdx.x;
    const float* WtU = Wt; const float* biasU = bias; float* CU = C;
    if (ntile >= nsplit) { ntile -= nsplit; WtU = Wt2; biasU = bias2; CU = C2; }

    const int mtile = blockIdx.y;
    const int batch = mtile / mtPerB;
    const int mloc  = mtile % mtPerB;
    const int nbase = (wid >> 1) * 64;   // 0 or 64
    const int mbase = (wid & 1) * 64;    // 0 or 64

    const float* Wrow = WtU + (size_t)batch * wtBStride + (size_t)ntile * 128 * Kd;
    const float* Arow = A + (size_t)mtile * 128 * Kd;

    // staging: per stage per operand 1024 16B-chunks; 128 threads -> 8 each
    int srcOff[8];
    uint32_t dstOff[8];
    #pragma unroll
    for (int i = 0; i < 8; i++) {
        int c = tid + i * 128;
        int r = c >> 3, c4 = c & 7;
        srcOff[i] = r * Kd + c4 * 4;
        dstOff[i] = (uint32_t)(r * (ROWSTRIDE * 4) + c4 * 16);
    }

    auto load_stage = [&](int it) {
        const uint32_t wbuf = sbase + (it % STG) * STAGE_BYTES;
        const uint32_t abuf = wbuf + TILE_BYTES;
        const float* wk = Wrow + it * 32;
        const float* ak = Arow + it * 32;
        #pragma unroll
        for (int i = 0; i < 8; i++) cp_async16(wbuf + dstOff[i], wk + srcOff[i]);
        #pragma unroll
        for (int i = 0; i < 8; i++) cp_async16(abuf + dstOff[i], ak + srcOff[i]);
    };

    float acc[4][8][4];
    #pragma unroll
    for (int i = 0; i < 4; i++)
        #pragma unroll
        for (int j = 0; j < 8; j++)
            #pragma unroll
            for (int e = 0; e < 4; e++) acc[i][j][e] = 0.f;

    #pragma unroll
    for (int p = 0; p < STG - 1; p++) { load_stage(p); cp_commit(); }

    const int NIT = Kd / 32;
    for (int it = 0; it < NIT; ++it) {
        cp_wait<STG - 2>();
        __syncthreads();
        if (it + STG - 1 < NIT) load_stage(it + STG - 1);
        cp_commit();

        const uint32_t* wt = (const uint32_t*)(smem + (it % STG) * STAGE_BYTES);
        const uint32_t* at = (const uint32_t*)(smem + (it % STG) * STAGE_BYTES + TILE_BYTES);

        #pragma unroll
        for (int ks = 0; ks < 4; ks++) {
            const int col = ks * 8 + tg;
            uint32_t afr[4][4];
            #pragma unroll
            for (int i = 0; i < 4; i++) {
                const int r0 = nbase + i * 16 + g;
                afr[i][0] = wt[r0 * ROWSTRIDE + col];
                afr[i][1] = wt[(r0 + 8) * ROWSTRIDE + col];
                afr[i][2] = wt[r0 * ROWSTRIDE + col + 4];
                afr[i][3] = wt[(r0 + 8) * ROWSTRIDE + col + 4];
            }
            uint32_t bfr[8][2];
            #pragma unroll
            for (int j = 0; j < 8; j++) {
                const int r = mbase + j * 8 + g;
                bfr[j][0] = at[r * ROWSTRIDE + col];
                bfr[j][1] = at[r * ROWSTRIDE + col + 4];
            }
            #pragma unroll
            for (int i = 0; i < 4; i++)
                #pragma unroll
                for (int j = 0; j < 8; j++)
                    mma_tf32(acc[i][j], afr[i], bfr[j]);
        }
    }

    // epilogue: transpose Ct[n][m] -> C[m][n] via smem, add bias
    __syncthreads();
    float* cs = (float*)smem;        // [128 n][129 m]
    #pragma unroll
    for (int i = 0; i < 4; i++) {
        #pragma unroll
        for (int j = 0; j < 8; j++) {
            const int n = nbase + i * 16 + g;
            const int m = mbase + j * 8 + tg * 2;
            cs[n * 129 + m]           = acc[i][j][0];
            cs[n * 129 + m + 1]       = acc[i][j][1];
            cs[(n + 8) * 129 + m]     = acc[i][j][2];
            cs[(n + 8) * 129 + m + 1] = acc[i][j][3];
        }
    }
    __syncthreads();

    const int m = tid;                      // 0..127: one output row per thread
    const size_t outRow = (size_t)batch * outBStride + outOff + mloc * 128 + m;
    const float* brow = biasU + ntile * 128;
    float* Crow = CU + outRow * NDIM + ntile * 128;
    #pragma unroll
    for (int q = 0; q < 32; q++) {
        float4 v;
        v.x = cs[(q * 4 + 0) * 129 + m] + brow[q * 4 + 0];
        v.y = cs[(q * 4 + 1) * 129 + m] + brow[q * 4 + 1];
        v.z = cs[(q * 4 + 2) * 129 + m] + brow[q * 4 + 2];
        v.w = cs[(q * 4 + 3) * 129 + m] + brow[q * 4 + 3];
        *(float4*)(Crow + q * 4) = v;
    }
}

// ---------------------------------------------------------------------------
// img -> tf32-rounded copy
// ---------------------------------------------------------------------------
__global__ __launch_bounds__(256)
void cvt_img(const float* __restrict__ in, float* __restrict__ out)
{
    const int i = blockIdx.x * 256 + threadIdx.x;
    float4 v = ((const float4*)in)[i];
    v.x = tf32r(v.x); v.y = tf32r(v.y); v.z = tf32r(v.z); v.w = tf32r(v.w);
    ((float4*)out)[i] = v;
}

// W [K,N] -> WT [N,K], tf32-rounded.
__global__ __launch_bounds__(256)
void transpose_cvt(const float* __restrict__ W, float* __restrict__ WT)
{
    __shared__ float t[32][33];
    const int x = blockIdx.x * 32 + threadIdx.x;
    const int y0 = blockIdx.y * 32 + threadIdx.y;
    #pragma unroll
    for (int i = 0; i < 32; i += 8)
        t[threadIdx.y + i][threadIdx.x] = W[(size_t)(y0 + i) * E_ + x];
    __syncthreads();
    const int x2 = blockIdx.y * 32 + threadIdx.x;
    const int y2 = blockIdx.x * 32 + threadIdx.y;
    #pragma unroll
    for (int i = 0; i < 32; i += 8)
        WT[(size_t)(y2 + i) * E_ + x2] = tf32r(t[threadIdx.x][threadIdx.y + i]);
}

// ---------------------------------------------------------------------------
// Tiny text projections
// ---------------------------------------------------------------------------
__global__ __launch_bounds__(256)
void small_proj(const float* __restrict__ text,
                const float* __restrict__ Wk, const float* __restrict__ bk,
                const float* __restrict__ Wv, const float* __restrict__ bv)
{
    const int b = blockIdx.y;
    const int n = blockIdx.x * 256 + threadIdx.x;
    __shared__ float ts[E_];
    for (int i = threadIdx.x; i < E_; i += 256) ts[i] = text[b * E_ + i];
    __syncthreads();
    float accK = 0.f, accV = 0.f;
    for (int k = 0; k < E_; k++) {
        const float t = ts[k];
        accK += t * Wk[(size_t)k * E_ + n];
        accV += t * Wv[(size_t)k * E_ + n];
    }
    g_kti[b * E_ + n] = accK + bk[n];
    g_vti[b * E_ + n] = accV + bv[n];
}

// ---------------------------------------------------------------------------
// Pt[b][n][(q*16+l)] = tf32( sum_d v_ti[b, l*64+d] * W_out[(q*64+d)*1024 + n] )
// ---------------------------------------------------------------------------
__global__ __launch_bounds__(256)
void compute_Pt(const float* __restrict__ W_out)
{
    const int n = blockIdx.x * 256 + threadIdx.x;
    const int ql = blockIdx.y;
    const int q = ql >> 4, l = ql & 15;

    __shared__ float vt[B_][D_];
    for (int i = threadIdx.x; i < B_ * D_; i += 256)
        vt[i / D_][i % D_] = g_vti[(i / D_) * E_ + l * 64 + (i % D_)];
    __syncthreads();

    float acc[B_];
    #pragma unroll
    for (int b = 0; b < B_; b++) acc[b] = 0.f;
    #pragma unroll 8
    for (int d = 0; d < D_; d++) {
        const float w = W_out[(size_t)(q * 64 + d) * NDIM + n];
        #pragma unroll
        for (int b = 0; b < B_; b++) acc[b] += w * vt[b][d];
    }
    #pragma unroll
    for (int b = 0; b < B_; b++)
        g_Pt[(size_t)b * (NDIM * 256) + (size_t)n * 256 + ql] = tf32r(acc[b]);
}

// ---------------------------------------------------------------------------
// Fused per-position attention, 2 positions/block.
// Writes img_out (tf32) to g_cat and att2 weights (tf32) to g_att2.
// ---------------------------------------------------------------------------
#define NPOS 2
#define PD 65

__global__ __launch_bounds__(256)
void attention_pos(const float* __restrict__ img, const float* __restrict__ text)
{
    const int n0 = blockIdx.x * NPOS;
    const int b = blockIdx.y;
    const int tid = threadIdx.x;

    __shared__ float4 xs4[NPOS][256], vs4[NPOS][256], txs4[256];
    __shared__ float ks[NPOS][H_ * PD], ktis[H_ * PD];
    __shared__ float att1[NPOS][H_][H_];

    const size_t r0 = (size_t)b * S_ + n0;
    {
        const int e = tid * 4, l = e >> 6, j = e & 63;
        #pragma unroll
        for (int p = 0; p < NPOS; p++) {
            xs4[p][tid] = ((const float4*)img)[(r0 + p) * 256 + tid];
            vs4[p][tid] = ((const float4*)g_vit)[(r0 + p) * 256 + tid];
            float4 vk = ((const float4*)g_kit)[(r0 + p) * 256 + tid];
            float* kp = &ks[p][l * PD + j];
            kp[0] = vk.x; kp[1] = vk.y; kp[2] = vk.z; kp[3] = vk.w;
        }
        txs4[tid] = ((const float4*)text)[b * 256 + tid];
        float4 vkt = ((const float4*)g_kti)[b * 256 + tid];
        float* kp = &ktis[l * PD + j];
        kp[0] = vkt.x; kp[1] = vkt.y; kp[2] = vkt.z; kp[3] = vkt.w;
    }
    __syncthreads();

    const int q = tid >> 4;
    const int l = tid & 15;
    const float* txq = (const float*)txs4 + q * 64;
    const float* x0q = (const float*)xs4[0] + q * 64;
    const float* x1q = (const float*)xs4[1] + q * 64;

    float s1a = 0.f, s1b = 0.f, s2a = 0.f, s2b = 0.f;
    #pragma unroll
    for (int j = 0; j < D_; j++) {
        const float tv  = txq[j];
        const float ktv = ktis[l * PD + j];
        s1a += tv * ks[0][l * PD + j];
        s1b += tv * ks[1][l * PD + j];
        s2a += x0q[j] * ktv;
        s2b += x1q[j] * ktv;
    }
    s1a *= 0.125f; s1b *= 0.125f; s2a *= 0.125f; s2b *= 0.125f;

    float m1a = s1a, m1b = s1b, m2a = s2a, m2b = s2b;
    #pragma unroll
    for (int o = 8; o > 0; o >>= 1) {
        m1a = fmaxf(m1a, __shfl_xor_sync(0xffffffffu, m1a, o));
        m1b = fmaxf(m1b, __shfl_xor_sync(0xffffffffu, m1b, o));
        m2a = fmaxf(m2a, __shfl_xor_sync(0xffffffffu, m2a, o));
        m2b = fmaxf(m2b, __shfl_xor_sync(0xffffffffu, m2b, o));
    }
    float e1a = expf(s1a - m1a), e1b = expf(s1b - m1b);
    float e2a = expf(s2a - m2a), e2b = expf(s2b - m2b);
    float z1a = e1a, z1b = e1b, z2a = e2a, z2b = e2b;
    #pragma unroll
    for (int o = 8; o > 0; o >>= 1) {
        z1a += __shfl_xor_sync(0xffffffffu, z1a, o);
        z1b += __shfl_xor_sync(0xffffffffu, z1b, o);
        z2a += __shfl_xor_sync(0xffffffffu, z2a, o);
        z2b += __shfl_xor_sync(0xffffffffu, z2b, o);
    }
    att1[0][q][l] = e1a / z1a;  att1[1][q][l] = e1b / z1b;
    g_att2[(r0 + 0) * 256 + tid] = tf32r(e2a / z2a);
    g_att2[(r0 + 1) * 256 + tid] = tf32r(e2b / z2b);
    __syncthreads();

    const int qq = tid >> 4;
    const int dv = tid & 15;
    float4* cat4 = (float4*)g_cat;
    #pragma unroll
    for (int p = 0; p < NPOS; p++) {
        float4 o1 = make_float4(0.f, 0.f, 0.f, 0.f);
        #pragma unroll
        for (int ll = 0; ll < H_; ll++) {
            const float a1 = att1[p][qq][ll];
            const float4 vv = vs4[p][ll * 16 + dv];
            o1.x += a1 * vv.x; o1.y += a1 * vv.y; o1.z += a1 * vv.z; o1.w += a1 * vv.w;
        }
        o1.x = tf32r(o1.x); o1.y = tf32r(o1.y); o1.z = tf32r(o1.z); o1.w = tf32r(o1.w);
        cat4[(r0 + p) * 256 + tid] = o1;
    }
}

// ---------------------------------------------------------------------------
extern "C" void kernel_launch(void* const* d_in, const int* in_sizes, int n_in,
                              void* d_out, int out_size)
{
    const float* img   = (const float*)d_in[0];
    const float* text  = (const float*)d_in[1];
    const float* W_kit = (const float*)d_in[2];
    const float* b_kit = (const float*)d_in[3];
    const float* W_vit = (const float*)d_in[4];
    const float* b_vit = (const float*)d_in[5];
    const float* W_kti = (const float*)d_in[6];
    const float* b_kti = (const float*)d_in[7];
    const float* W_vti = (const float*)d_in[8];
    const float* b_vti = (const float*)d_in[9];
    const float* W_out = (const float*)d_in[10];
    const float* b_out = (const float*)d_in[11];
    float* out = (float*)d_out;

    float *a32, *kit, *vit, *cat, *att2, *Pt, *wkT, *wvT, *woT;
    cudaGetSymbolAddress((void**)&a32, g_a32);
    cudaGetSymbolAddress((void**)&kit, g_kit);
    cudaGetSymbolAddress((void**)&vit, g_vit);
    cudaGetSymbolAddress((void**)&cat, g_cat);
    cudaGetSymbolAddress((void**)&att2, g_att2);
    cudaGetSymbolAddress((void**)&Pt, g_Pt);
    cudaGetSymbolAddress((void**)&wkT, g_wkT);
    cudaGetSymbolAddress((void**)&wvT, g_wvT);
    cudaGetSymbolAddress((void**)&woT, g_woT);

    cudaFuncSetAttribute(gemm_tc, cudaFuncAttributeMaxDynamicSharedMemorySize, GEMM_SMEM);

    // operand preparation
    cvt_img<<<(M1 * E_ / 4) / 256, 256>>>(img, a32);
    transpose_cvt<<<dim3(32, 32), dim3(32, 8)>>>(W_kit, wkT);
    transpose_cvt<<<dim3(32, 32), dim3(32, 8)>>>(W_vit, wvT);
    transpose_cvt<<<dim3(32, 32), dim3(32, 8)>>>(W_out, woT);
    small_proj<<<dim3(E_ / 256, B_), 256>>>(text, W_kti, b_kti, W_vti, b_vti);
    compute_Pt<<<dim3(4, 256), 256>>>(W_out);

    // fused k_it + v_it projections (shared A block across 16 n-tiles)
    gemm_tc<<<dim3(16, M1 / 128), 128, GEMM_SMEM>>>(
        a32, wkT, b_kit, kit, wvT, b_vit, vit,
        1024, 8, 256, 0, 0, 0);

    // fused attention -> img_out (g_cat) + att2 weights
    attention_pos<<<dim3(S_ / NPOS, B_), 256>>>(img, text);

    // final projection, img half: rows b*8192 + n
    gemm_tc<<<dim3(8, M1 / 128), 128, GEMM_SMEM>>>(
        cat, woT, b_out, out, woT, b_out, out,
        1024, 8, 32, 8192, 0, 0);
    // final projection, text half (factored): K=256, rows b*8192 + 4096 + n
    gemm_tc<<<dim3(8, M1 / 128), 128, GEMM_SMEM>>>(
        att2, Pt, b_out, out, Pt, b_out, out,
        256, 8, 32, 8192, 4096, 256 * 1024);
}

// round 7
// speedup vs baseline: 4.6375x; 1.2486x over previous
#include <cuda_runtime.h>
#include <cstdint>
#include <math.h>

// Problem constants
#define B_   8
#define S_   4096
#define E_   1024
#define H_   16
#define D_   64
#define M1   (B_ * S_)        // 32768

// Scratch (device globals; zero-initialized at module load)
__device__ float g_a32[M1 * E_];    // img rounded to tf32
__device__ float g_vit[M1 * E_];
__device__ float g_kti[B_ * E_];
__device__ float g_vti[B_ * E_];
__device__ float g_cat[M1 * E_];    // img_out (tf32-rounded)
__device__ float g_s1[M1 * 256];    // img-attention raw scores
__device__ float g_att2[M1 * 256];  // text attention weights (tf32)
__device__ float g_Qt[B_ * 256 * E_];   // Q^T per batch: [b][(q,l)][e] tf32
__device__ float g_c[B_ * 256];     // score bias correction c[b][(q,l)]
__device__ float g_Pt[B_ * E_ * 256];   // P^T per batch: [b][n][(q,l)] tf32
__device__ float g_wkT[E_ * E_];    // W_kit^T (tf32), [N,K]
__device__ float g_wvT[E_ * E_];
__device__ float g_woT[E_ * E_];
__device__ float g_zero[1024];      // zero bias

// ---------------------------------------------------------------------------
// helpers
// ---------------------------------------------------------------------------
__device__ __forceinline__ uint32_t smem_u32(const void* p) {
    uint32_t a;
    asm("{ .reg .u64 t; cvta.to.shared.u64 t, %1; cvt.u32.u64 %0, t; }" : "=r"(a) : "l"(p));
    return a;
}
__device__ __forceinline__ float tf32r(float x) {
    uint32_t u; asm("cvt.rna.tf32.f32 %0, %1;" : "=r"(u) : "f"(x));
    return __uint_as_float(u);
}
__device__ __forceinline__ void cp_async16(uint32_t dst, const void* src) {
    asm volatile("cp.async.cg.shared.global [%0], [%1], 16;" :: "r"(dst), "l"(src) : "memory");
}
__device__ __forceinline__ void cp_commit() {
    asm volatile("cp.async.commit_group;" ::: "memory");
}
template <int N> __device__ __forceinline__ void cp_wait() {
    asm volatile("cp.async.wait_group %0;" :: "n"(N) : "memory");
}
__device__ __forceinline__ void mma_tf32(float* d, const uint32_t* a, const uint32_t* b) {
    asm volatile(
        "mma.sync.aligned.m16n8k8.row.col.f32.tf32.tf32.f32 "
        "{%0,%1,%2,%3}, {%4,%5,%6,%7}, {%8,%9}, {%0,%1,%2,%3};"
        : "+f"(d[0]), "+f"(d[1]), "+f"(d[2]), "+f"(d[3])
        : "r"(a[0]), "r"(a[1]), "r"(a[2]), "r"(a[3]), "r"(b[0]), "r"(b[1]));
}

// ---------------------------------------------------------------------------
// Tensor-core tf32 GEMM, dual-weight split:
//   ntile' = blockIdx.x; side 1 if ntile' < nsplit else side 2.
//   C_rows = A[M,Kd] @ Wt[Nout,Kd]^T + bias
// Output row: batch*outBStride + outOff + (mtile%mtPerB)*128 + m
// Wt per batch: Wt + batch*wtB.  batch = mtile / mtPerB.
// CTA tile 128x128, 4 warps (warp tile n64 x m64), 32-wide K stages,
// 3-stage cp.async pipeline, 2 CTAs/SM.
// ---------------------------------------------------------------------------
#define STG 3
#define ROWSTRIDE 36
#define TILE_BYTES (128 * ROWSTRIDE * 4)
#define STAGE_BYTES (2 * TILE_BYTES)
#define GEMM_SMEM (STG * STAGE_BYTES)      // 110592

__global__ __launch_bounds__(128, 2)
void gemm_tc(const float* __restrict__ A,
             const float* __restrict__ Wt,  const float* __restrict__ bias,
             float* __restrict__ C,  int Nout,  int wtB,
             const float* __restrict__ Wt2, const float* __restrict__ bias2,
             float* __restrict__ C2, int Nout2, int wtB2,
             int Kd, int nsplit, int mtPerB, int outBStride, int outOff)
{
    extern __shared__ char smem[];
    const uint32_t sbase = smem_u32(smem);
    const int tid = threadIdx.x;
    const int wid = tid >> 5, lane = tid & 31;
    const int g = lane >> 2, tg = lane & 3;

    int ntile = blockIdx.x;
    const float* WtU = Wt; const float* biasU = bias; float* CU = C;
    int NoutU = Nout, wtBU = wtB;
    if (ntile >= nsplit) {
        ntile -= nsplit; WtU = Wt2; biasU = bias2; CU = C2; NoutU = Nout2; wtBU = wtB2;
    }

    const int mtile = blockIdx.y;
    const int batch = mtile / mtPerB;
    const int mloc  = mtile % mtPerB;
    const int nbase = (wid >> 1) * 64;
    const int mbase = (wid & 1) * 64;

    const float* Wrow = WtU + (size_t)batch * wtBU + (size_t)ntile * 128 * Kd;
    const float* Arow = A + (size_t)mtile * 128 * Kd;

    int srcOff[8];
    uint32_t dstOff[8];
    #pragma unroll
    for (int i = 0; i < 8; i++) {
        int c = tid + i * 128;
        int r = c >> 3, c4 = c & 7;
        srcOff[i] = r * Kd + c4 * 4;
        dstOff[i] = (uint32_t)(r * (ROWSTRIDE * 4) + c4 * 16);
    }

    auto load_stage = [&](int it) {
        const uint32_t wbuf = sbase + (it % STG) * STAGE_BYTES;
        const uint32_t abuf = wbuf + TILE_BYTES;
        const float* wk = Wrow + it * 32;
        const float* ak = Arow + it * 32;
        #pragma unroll
        for (int i = 0; i < 8; i++) cp_async16(wbuf + dstOff[i], wk + srcOff[i]);
        #pragma unroll
        for (int i = 0; i < 8; i++) cp_async16(abuf + dstOff[i], ak + srcOff[i]);
    };

    float acc[4][8][4];
    #pragma unroll
    for (int i = 0; i < 4; i++)
        #pragma unroll
        for (int j = 0; j < 8; j++)
            #pragma unroll
            for (int e = 0; e < 4; e++) acc[i][j][e] = 0.f;

    #pragma unroll
    for (int p = 0; p < STG - 1; p++) { load_stage(p); cp_commit(); }

    const int NIT = Kd / 32;
    for (int it = 0; it < NIT; ++it) {
        cp_wait<STG - 2>();
        __syncthreads();
        if (it + STG - 1 < NIT) load_stage(it + STG - 1);
        cp_commit();

        const uint32_t* wt = (const uint32_t*)(smem + (it % STG) * STAGE_BYTES);
        const uint32_t* at = (const uint32_t*)(smem + (it % STG) * STAGE_BYTES + TILE_BYTES);

        #pragma unroll
        for (int ks = 0; ks < 4; ks++) {
            const int col = ks * 8 + tg;
            uint32_t afr[4][4];
            #pragma unroll
            for (int i = 0; i < 4; i++) {
                const int r0 = nbase + i * 16 + g;
                afr[i][0] = wt[r0 * ROWSTRIDE + col];
                afr[i][1] = wt[(r0 + 8) * ROWSTRIDE + col];
                afr[i][2] = wt[r0 * ROWSTRIDE + col + 4];
                afr[i][3] = wt[(r0 + 8) * ROWSTRIDE + col + 4];
            }
            uint32_t bfr[8][2];
            #pragma unroll
            for (int j = 0; j < 8; j++) {
                const int r = mbase + j * 8 + g;
                bfr[j][0] = at[r * ROWSTRIDE + col];
                bfr[j][1] = at[r * ROWSTRIDE + col + 4];
            }
            #pragma unroll
            for (int i = 0; i < 4; i++)
                #pragma unroll
                for (int j = 0; j < 8; j++)
                    mma_tf32(acc[i][j], afr[i], bfr[j]);
        }
    }

    // epilogue: transpose Ct[n][m] -> C[m][n] via smem, add bias
    __syncthreads();
    float* cs = (float*)smem;        // [128 n][129 m]
    #pragma unroll
    for (int i = 0; i < 4; i++) {
        #pragma unroll
        for (int j = 0; j < 8; j++) {
            const int n = nbase + i * 16 + g;
            const int m = mbase + j * 8 + tg * 2;
            cs[n * 129 + m]           = acc[i][j][0];
            cs[n * 129 + m + 1]       = acc[i][j][1];
            cs[(n + 8) * 129 + m]     = acc[i][j][2];
            cs[(n + 8) * 129 + m + 1] = acc[i][j][3];
        }
    }
    __syncthreads();

    const int m = tid;
    const size_t outRow = (size_t)batch * outBStride + outOff + mloc * 128 + m;
    const float* brow = biasU + ntile * 128;
    float* Crow = CU + outRow * NoutU + ntile * 128;
    #pragma unroll
    for (int q = 0; q < 32; q++) {
        float4 v;
        v.x = cs[(q * 4 + 0) * 129 + m] + brow[q * 4 + 0];
        v.y = cs[(q * 4 + 1) * 129 + m] + brow[q * 4 + 1];
        v.z = cs[(q * 4 + 2) * 129 + m] + brow[q * 4 + 2];
        v.w = cs[(q * 4 + 3) * 129 + m] + brow[q * 4 + 3];
        *(float4*)(Crow + q * 4) = v;
    }
}

// ---------------------------------------------------------------------------
// img -> tf32-rounded copy
// ---------------------------------------------------------------------------
__global__ __launch_bounds__(256)
void cvt_img(const float* __restrict__ in, float* __restrict__ out)
{
    const int i = blockIdx.x * 256 + threadIdx.x;
    float4 v = ((const float4*)in)[i];
    v.x = tf32r(v.x); v.y = tf32r(v.y); v.z = tf32r(v.z); v.w = tf32r(v.w);
    ((float4*)out)[i] = v;
}

// W [K,N] -> WT [N,K], tf32-rounded.
__global__ __launch_bounds__(256)
void transpose_cvt(const float* __restrict__ W, float* __restrict__ WT)
{
    __shared__ float t[32][33];
    const int x = blockIdx.x * 32 + threadIdx.x;
    const int y0 = blockIdx.y * 32 + threadIdx.y;
    #pragma unroll
    for (int i = 0; i < 32; i += 8)
        t[threadIdx.y + i][threadIdx.x] = W[(size_t)(y0 + i) * E_ + x];
    __syncthreads();
    const int x2 = blockIdx.y * 32 + threadIdx.x;
    const int y2 = blockIdx.x * 32 + threadIdx.y;
    #pragma unroll
    for (int i = 0; i < 32; i += 8)
        WT[(size_t)(y2 + i) * E_ + x2] = tf32r(t[threadIdx.x][threadIdx.y + i]);
}

// ---------------------------------------------------------------------------
// Tiny text projections
// ---------------------------------------------------------------------------
__global__ __launch_bounds__(256)
void small_proj(const float* __restrict__ text,
                const float* __restrict__ Wk, const float* __restrict__ bk,
                const float* __restrict__ Wv, const float* __restrict__ bv)
{
    const int b = blockIdx.y;
    const int n = blockIdx.x * 256 + threadIdx.x;
    __shared__ float ts[E_];
    for (int i = threadIdx.x; i < E_; i += 256) ts[i] = text[b * E_ + i];
    __syncthreads();
    float accK = 0.f, accV = 0.f;
    for (int k = 0; k < E_; k++) {
        const float t = ts[k];
        accK += t * Wk[(size_t)k * E_ + n];
        accV += t * Wv[(size_t)k * E_ + n];
    }
    g_kti[b * E_ + n] = accK + bk[n];
    g_vti[b * E_ + n] = accV + bv[n];
}

// ---------------------------------------------------------------------------
// Qt[b][(q*16+l)][e] = tf32( sum_d text[b, q*64+d] * wkT[(l*64+d)][e] )
// grid (4, 256=(q,l)), 256 threads = e within chunk; 8 batches in regs.
// ---------------------------------------------------------------------------
__global__ __launch_bounds__(256)
void compute_Q(const float* __restrict__ text)
{
    const int e = blockIdx.x * 256 + threadIdx.x;
    const int ql = blockIdx.y;
    const int q = ql >> 4, l = ql & 15;

    __shared__ float tx[B_][D_];
    for (int i = threadIdx.x; i < B_ * D_; i += 256)
        tx[i / D_][i % D_] = text[(i / D_) * E_ + q * 64 + (i % D_)];
    __syncthreads();

    float acc[B_];
    #pragma unroll
    for (int b = 0; b < B_; b++) acc[b] = 0.f;
    #pragma unroll 8
    for (int d = 0; d < D_; d++) {
        const float w = g_wkT[(size_t)(l * 64 + d) * E_ + e];
        #pragma unroll
        for (int b = 0; b < B_; b++) acc[b] += w * tx[b][d];
    }
    #pragma unroll
    for (int b = 0; b < B_; b++)
        g_Qt[(size_t)b * (256 * E_) + (size_t)ql * E_ + e] = tf32r(acc[b]);
}

// c[b][(q,l)] = sum_d text[b, q*64+d] * b_kit[l*64+d].  grid(B_), 256 thr.
__global__ __launch_bounds__(256)
void compute_c(const float* __restrict__ text, const float* __restrict__ bk)
{
    const int b = blockIdx.x;
    const int ql = threadIdx.x;
    const int q = ql >> 4, l = ql & 15;
    float acc = 0.f;
    #pragma unroll 8
    for (int d = 0; d < D_; d++)
        acc += text[b * E_ + q * 64 + d] * bk[l * 64 + d];
    g_c[b * 256 + ql] = acc;
}

// ---------------------------------------------------------------------------
// Pt[b][n][(q*16+l)] = tf32( sum_d v_ti[b, l*64+d] * W_out[(q*64+d)*1024 + n] )
// ---------------------------------------------------------------------------
__global__ __launch_bounds__(256)
void compute_Pt(const float* __restrict__ W_out)
{
    const int n = blockIdx.x * 256 + threadIdx.x;
    const int ql = blockIdx.y;
    const int q = ql >> 4, l = ql & 15;

    __shared__ float vt[B_][D_];
    for (int i = threadIdx.x; i < B_ * D_; i += 256)
        vt[i / D_][i % D_] = g_vti[(i / D_) * E_ + l * 64 + (i % D_)];
    __syncthreads();

    float acc[B_];
    #pragma unroll
    for (int b = 0; b < B_; b++) acc[b] = 0.f;
    #pragma unroll 8
    for (int d = 0; d < D_; d++) {
        const float w = W_out[(size_t)(q * 64 + d) * E_ + n];
        #pragma unroll
        for (int b = 0; b < B_; b++) acc[b] += w * vt[b][d];
    }
    #pragma unroll
    for (int b = 0; b < B_; b++)
        g_Pt[(size_t)b * (E_ * 256) + (size_t)n * 256 + ql] = tf32r(acc[b]);
}

// ---------------------------------------------------------------------------
// Fused per-position attention, 2 positions/block.
// s1 comes precomputed from the score GEMM (+c correction).
// Writes img_out (tf32) to g_cat and att2 weights (tf32) to g_att2.
// ---------------------------------------------------------------------------
#define NPOS 2
#define PD 65

__global__ __launch_bounds__(256)
void attention_pos(const float* __restrict__ img)
{
    const int n0 = blockIdx.x * NPOS;
    const int b = blockIdx.y;
    const int tid = threadIdx.x;

    __shared__ float4 xs4[NPOS][256], vs4[NPOS][256];
    __shared__ float ktis[H_ * PD], cb[256];
    __shared__ float att1[NPOS][H_][H_];

    const size_t r0 = (size_t)b * S_ + n0;
    {
        const int e = tid * 4, l = e >> 6, j = e & 63;
        #pragma unroll
        for (int p = 0; p < NPOS; p++) {
            xs4[p][tid] = ((const float4*)img)[(r0 + p) * 256 + tid];
            vs4[p][tid] = ((const float4*)g_vit)[(r0 + p) * 256 + tid];
        }
        float4 vkt = ((const float4*)g_kti)[b * 256 + tid];
        float* kp = &ktis[l * PD + j];
        kp[0] = vkt.x; kp[1] = vkt.y; kp[2] = vkt.z; kp[3] = vkt.w;
        cb[tid] = g_c[b * 256 + tid];
    }
    // raw img-attention scores (coalesced; tid == (q,l))
    float s1a = g_s1[(r0 + 0) * 256 + tid];
    float s1b = g_s1[(r0 + 1) * 256 + tid];
    __syncthreads();

    const int q = tid >> 4;
    const int l = tid & 15;
    const float* x0q = (const float*)xs4[0] + q * 64;
    const float* x1q = (const float*)xs4[1] + q * 64;

    s1a = (s1a + cb[tid]) * 0.125f;
    s1b = (s1b + cb[tid]) * 0.125f;

    float s2a = 0.f, s2b = 0.f;
    #pragma unroll
    for (int j = 0; j < D_; j++) {
        const float ktv = ktis[l * PD + j];
        s2a += x0q[j] * ktv;
        s2b += x1q[j] * ktv;
    }
    s2a *= 0.125f; s2b *= 0.125f;

    float m1a = s1a, m1b = s1b, m2a = s2a, m2b = s2b;
    #pragma unroll
    for (int o = 8; o > 0; o >>= 1) {
        m1a = fmaxf(m1a, __shfl_xor_sync(0xffffffffu, m1a, o));
        m1b = fmaxf(m1b, __shfl_xor_sync(0xffffffffu, m1b, o));
        m2a = fmaxf(m2a, __shfl_xor_sync(0xffffffffu, m2a, o));
        m2b = fmaxf(m2b, __shfl_xor_sync(0xffffffffu, m2b, o));
    }
    float e1a = expf(s1a - m1a), e1b = expf(s1b - m1b);
    float e2a = expf(s2a - m2a), e2b = expf(s2b - m2b);
    float z1a = e1a, z1b = e1b, z2a = e2a, z2b = e2b;
    #pragma unroll
    for (int o = 8; o > 0; o >>= 1) {
        z1a += __shfl_xor_sync(0xffffffffu, z1a, o);
        z1b += __shfl_xor_sync(0xffffffffu, z1b, o);
        z2a += __shfl_xor_sync(0xffffffffu, z2a, o);
        z2b += __shfl_xor_sync(0xffffffffu, z2b, o);
    }
    att1[0][q][l] = e1a / z1a;  att1[1][q][l] = e1b / z1b;
    g_att2[(r0 + 0) * 256 + tid] = tf32r(e2a / z2a);
    g_att2[(r0 + 1) * 256 + tid] = tf32r(e2b / z2b);
    __syncthreads();

    const int qq = tid >> 4;
    const int dv = tid & 15;
    float4* cat4 = (float4*)g_cat;
    #pragma unroll
    for (int p = 0; p < NPOS; p++) {
        float4 o1 = make_float4(0.f, 0.f, 0.f, 0.f);
        #pragma unroll
        for (int ll = 0; ll < H_; ll++) {
            const float a1 = att1[p][qq][ll];
            const float4 vv = vs4[p][ll * 16 + dv];
            o1.x += a1 * vv.x; o1.y += a1 * vv.y; o1.z += a1 * vv.z; o1.w += a1 * vv.w;
        }
        o1.x = tf32r(o1.x); o1.y = tf32r(o1.y); o1.z = tf32r(o1.z); o1.w = tf32r(o1.w);
        cat4[(r0 + p) * 256 + tid] = o1;
    }
}

// ---------------------------------------------------------------------------
extern "C" void kernel_launch(void* const* d_in, const int* in_sizes, int n_in,
                              void* d_out, int out_size)
{
    const float* img   = (const float*)d_in[0];
    const float* text  = (const float*)d_in[1];
    const float* W_kit = (const float*)d_in[2];
    const float* b_kit = (const float*)d_in[3];
    const float* W_vit = (const float*)d_in[4];
    const float* b_vit = (const float*)d_in[5];
    const float* W_kti = (const float*)d_in[6];
    const float* b_kti = (const float*)d_in[7];
    const float* W_vti = (const float*)d_in[8];
    const float* b_vti = (const float*)d_in[9];
    const float* W_out = (const float*)d_in[10];
    const float* b_out = (const float*)d_in[11];
    float* out = (float*)d_out;

    float *a32, *vit, *cat, *s1, *att2, *Qt, *Pt, *wkT, *wvT, *woT, *zero;
    cudaGetSymbolAddress((void**)&a32, g_a32);
    cudaGetSymbolAddress((void**)&vit, g_vit);
    cudaGetSymbolAddress((void**)&cat, g_cat);
    cudaGetSymbolAddress((void**)&s1, g_s1);
    cudaGetSymbolAddress((void**)&att2, g_att2);
    cudaGetSymbolAddress((void**)&Qt, g_Qt);
    cudaGetSymbolAddress((void**)&Pt, g_Pt);
    cudaGetSymbolAddress((void**)&wkT, g_wkT);
    cudaGetSymbolAddress((void**)&wvT, g_wvT);
    cudaGetSymbolAddress((void**)&woT, g_woT);
    cudaGetSymbolAddress((void**)&zero, g_zero);

    cudaFuncSetAttribute(gemm_tc, cudaFuncAttributeMaxDynamicSharedMemorySize, GEMM_SMEM);

    // operand preparation
    cvt_img<<<(M1 * E_ / 4) / 256, 256>>>(img, a32);
    transpose_cvt<<<dim3(32, 32), dim3(32, 8)>>>(W_kit, wkT);
    transpose_cvt<<<dim3(32, 32), dim3(32, 8)>>>(W_vit, wvT);
    transpose_cvt<<<dim3(32, 32), dim3(32, 8)>>>(W_out, woT);
    small_proj<<<dim3(E_ / 256, B_), 256>>>(text, W_kti, b_kti, W_vti, b_vti);
    compute_Q<<<dim3(4, 256), 256>>>(text);
    compute_c<<<B_, 256>>>(text, b_kit);
    compute_Pt<<<dim3(4, 256), 256>>>(W_out);

    // fused: v_it projection (side 1, 8 n-tiles) + img-attn scores (side 2, 2 n-tiles)
    gemm_tc<<<dim3(10, M1 / 128), 128, GEMM_SMEM>>>(
        a32,
        wvT, b_vit, vit, 1024, 0,
        Qt, zero, s1, 256, 256 * E_,
        1024, 8, 32, 4096, 0);

    // fused attention -> img_out (g_cat) + att2 weights
    attention_pos<<<dim3(S_ / NPOS, B_), 256>>>(img);

    // final projection, img half: rows b*8192 + n
    gemm_tc<<<dim3(8, M1 / 128), 128, GEMM_SMEM>>>(
        cat,
        woT, b_out, out, 1024, 0,
        woT, b_out, out, 1024, 0,
        1024, 8, 32, 8192, 0);

    // final projection, text half (factored): K=256, rows b*8192 + 4096 + n
    gemm_tc<<<dim3(8, M1 / 128), 128, GEMM_SMEM>>>(
        att2,
        Pt, b_out, out, 1024, 256 * E_,
        Pt, b_out, out, 1024, 256 * E_,
        256, 8, 32, 8192, 4096);
}

// round 8
// speedup vs baseline: 6.9175x; 1.4916x over previous
#include <cuda_runtime.h>
#include <cuda_fp16.h>
#include <cstdint>
#include <math.h>

// Problem constants
#define B_   8
#define S_   4096
#define E_   1024
#define H_   16
#define D_   64
#define M1   (B_ * S_)        // 32768

// Scratch (device globals)
__device__ __half g_a16[M1 * E_];    // img in fp16
__device__ float  g_vit[M1 * E_];
__device__ float  g_kti[B_ * E_];
__device__ float  g_vti[B_ * E_];
__device__ __half g_cat[M1 * E_];    // img_out in fp16
__device__ float  g_s1[M1 * 256];    // img-attention raw scores (fp32)
__device__ __half g_att2[M1 * 256];  // text attention weights (fp16)
__device__ __half g_Qt[B_ * 256 * E_];   // Q^T per batch [b][(q,l)][e]
__device__ float  g_c[B_ * 256];     // score bias correction
__device__ __half g_Pt[B_ * E_ * 256];   // P^T per batch [b][n][(q,l)]
__device__ float  g_wkT[E_ * E_];    // W_kit^T fp32 (feeds compute_Q)
__device__ __half g_wvT[E_ * E_];
__device__ __half g_woT[E_ * E_];
__device__ float  g_zero[1024];      // zero bias

// ---------------------------------------------------------------------------
// helpers
// ---------------------------------------------------------------------------
__device__ __forceinline__ uint32_t smem_u32(const void* p) {
    uint32_t a;
    asm("{ .reg .u64 t; cvta.to.shared.u64 t, %1; cvt.u32.u64 %0, t; }" : "=r"(a) : "l"(p));
    return a;
}
__device__ __forceinline__ void cp_async16(uint32_t dst, const void* src) {
    asm volatile("cp.async.cg.shared.global [%0], [%1], 16;" :: "r"(dst), "l"(src) : "memory");
}
__device__ __forceinline__ void cp_commit() {
    asm volatile("cp.async.commit_group;" ::: "memory");
}
template <int N> __device__ __forceinline__ void cp_wait() {
    asm volatile("cp.async.wait_group %0;" :: "n"(N) : "memory");
}
__device__ __forceinline__ void mma_f16(float* d, const uint32_t* a, const uint32_t* b) {
    asm volatile(
        "mma.sync.aligned.m16n8k16.row.col.f32.f16.f16.f32 "
        "{%0,%1,%2,%3}, {%4,%5,%6,%7}, {%8,%9}, {%0,%1,%2,%3};"
        : "+f"(d[0]), "+f"(d[1]), "+f"(d[2]), "+f"(d[3])
        : "r"(a[0]), "r"(a[1]), "r"(a[2]), "r"(a[3]), "r"(b[0]), "r"(b[1]));
}

// ---------------------------------------------------------------------------
// Tensor-core fp16 GEMM (fp32 accum), dual-weight split:
//   ntile' = blockIdx.x; side 1 if ntile' < nsplit else side 2.
//   C_rows = A[M,Kd] @ Wt[Nout,Kd]^T + bias     (A, Wt fp16; C, bias fp32)
// Output row: batch*outBStride + outOff + (mtile%mtPerB)*128 + m
// Wt per batch: Wt + batch*wtB.  batch = mtile / mtPerB.
// CTA tile 128x128, 4 warps (warp tile n64 x m64), K=64 per stage,
// 3-stage cp.async pipeline, 2 CTAs/SM.
// ---------------------------------------------------------------------------
#define STG 3
#define ROWH 72                            // halfs per smem row (144B; conflict-free)
#define TILE_BYTES (128 * ROWH * 2)        // 18432
#define STAGE_BYTES (2 * TILE_BYTES)       // 36864
#define GEMM_SMEM (STG * STAGE_BYTES)      // 110592

__global__ __launch_bounds__(128, 2)
void gemm_tc(const __half* __restrict__ A,
             const __half* __restrict__ Wt,  const float* __restrict__ bias,
             float* __restrict__ C,  int Nout,  int wtB,
             const __half* __restrict__ Wt2, const float* __restrict__ bias2,
             float* __restrict__ C2, int Nout2, int wtB2,
             int Kd, int nsplit, int mtPerB, int outBStride, int outOff)
{
    extern __shared__ char smem[];
    const uint32_t sbase = smem_u32(smem);
    const int tid = threadIdx.x;
    const int wid = tid >> 5, lane = tid & 31;
    const int g = lane >> 2, tg = lane & 3;

    int ntile = blockIdx.x;
    const __half* WtU = Wt; const float* biasU = bias; float* CU = C;
    int NoutU = Nout, wtBU = wtB;
    if (ntile >= nsplit) {
        ntile -= nsplit; WtU = Wt2; biasU = bias2; CU = C2; NoutU = Nout2; wtBU = wtB2;
    }

    const int mtile = blockIdx.y;
    const int batch = mtile / mtPerB;
    const int mloc  = mtile % mtPerB;
    const int nbase = (wid >> 1) * 64;
    const int mbase = (wid & 1) * 64;

    const __half* Wrow = WtU + (size_t)batch * wtBU + (size_t)ntile * 128 * Kd;
    const __half* Arow = A + (size_t)mtile * 128 * Kd;

    // staging: per stage per operand 128 rows x 8 chunks(16B = 8 halfs);
    // 1024 chunks, 128 threads -> 8 each
    int srcOff[8];
    uint32_t dstOff[8];
    #pragma unroll
    for (int i = 0; i < 8; i++) {
        int c = tid + i * 128;
        int r = c >> 3, c8 = c & 7;
        srcOff[i] = r * Kd + c8 * 8;                 // halfs
        dstOff[i] = (uint32_t)(r * (ROWH * 2) + c8 * 16);
    }

    auto load_stage = [&](int it) {
        const uint32_t wbuf = sbase + (it % STG) * STAGE_BYTES;
        const uint32_t abuf = wbuf + TILE_BYTES;
        const __half* wk = Wrow + it * 64;
        const __half* ak = Arow + it * 64;
        #pragma unroll
        for (int i = 0; i < 8; i++) cp_async16(wbuf + dstOff[i], wk + srcOff[i]);
        #pragma unroll
        for (int i = 0; i < 8; i++) cp_async16(abuf + dstOff[i], ak + srcOff[i]);
    };

    float acc[4][8][4];
    #pragma unroll
    for (int i = 0; i < 4; i++)
        #pragma unroll
        for (int j = 0; j < 8; j++)
            #pragma unroll
            for (int e = 0; e < 4; e++) acc[i][j][e] = 0.f;

    #pragma unroll
    for (int p = 0; p < STG - 1; p++) { load_stage(p); cp_commit(); }

    const int NIT = Kd / 64;
    for (int it = 0; it < NIT; ++it) {
        cp_wait<STG - 2>();
        __syncthreads();
        if (it + STG - 1 < NIT) load_stage(it + STG - 1);
        cp_commit();

        // uint32 views; row stride in uint32 = ROWH/2 = 36
        const uint32_t* wt = (const uint32_t*)(smem + (it % STG) * STAGE_BYTES);
        const uint32_t* at = (const uint32_t*)(smem + (it % STG) * STAGE_BYTES + TILE_BYTES);

        #pragma unroll
        for (int ks = 0; ks < 4; ks++) {              // 4 x k16 per stage
            const int col = ks * 8 + tg;              // uint32 col (= 2 halfs)
            uint32_t afr[4][4];
            #pragma unroll
            for (int i = 0; i < 4; i++) {
                const int r0 = nbase + i * 16 + g;
                afr[i][0] = wt[r0 * 36 + col];            // row g,   k 2tg..2tg+1
                afr[i][1] = wt[(r0 + 8) * 36 + col];      // row g+8
                afr[i][2] = wt[r0 * 36 + col + 4];        // row g,   k +8
                afr[i][3] = wt[(r0 + 8) * 36 + col + 4];  // row g+8, k +8
            }
            uint32_t bfr[8][2];
            #pragma unroll
            for (int j = 0; j < 8; j++) {
                const int r = mbase + j * 8 + g;
                bfr[j][0] = at[r * 36 + col];
                bfr[j][1] = at[r * 36 + col + 4];
            }
            #pragma unroll
            for (int i = 0; i < 4; i++)
                #pragma unroll
                for (int j = 0; j < 8; j++)
                    mma_f16(acc[i][j], afr[i], bfr[j]);
        }
    }

    // epilogue: transpose Ct[n][m] -> C[m][n] via smem, add bias
    __syncthreads();
    float* cs = (float*)smem;        // [128 n][129 m]
    #pragma unroll
    for (int i = 0; i < 4; i++) {
        #pragma unroll
        for (int j = 0; j < 8; j++) {
            const int n = nbase + i * 16 + g;
            const int m = mbase + j * 8 + tg * 2;
            cs[n * 129 + m]           = acc[i][j][0];
            cs[n * 129 + m + 1]       = acc[i][j][1];
            cs[(n + 8) * 129 + m]     = acc[i][j][2];
            cs[(n + 8) * 129 + m + 1] = acc[i][j][3];
        }
    }
    __syncthreads();

    const int m = tid;
    const size_t outRow = (size_t)batch * outBStride + outOff + mloc * 128 + m;
    const float* brow = biasU + ntile * 128;
    float* Crow = CU + outRow * NoutU + ntile * 128;
    #pragma unroll
    for (int q = 0; q < 32; q++) {
        float4 v;
        v.x = cs[(q * 4 + 0) * 129 + m] + brow[q * 4 + 0];
        v.y = cs[(q * 4 + 1) * 129 + m] + brow[q * 4 + 1];
        v.z = cs[(q * 4 + 2) * 129 + m] + brow[q * 4 + 2];
        v.w = cs[(q * 4 + 3) * 129 + m] + brow[q * 4 + 3];
        *(float4*)(Crow + q * 4) = v;
    }
}

// ---------------------------------------------------------------------------
// img (fp32) -> fp16 copy
// ---------------------------------------------------------------------------
__global__ __launch_bounds__(256)
void cvt_img(const float* __restrict__ in, __half* __restrict__ out)
{
    const int i = blockIdx.x * 256 + threadIdx.x;
    float4 v = ((const float4*)in)[i];
    __half2 h01 = __floats2half2_rn(v.x, v.y);
    __half2 h23 = __floats2half2_rn(v.z, v.w);
    ((__half2*)out)[i * 2]     = h01;
    ((__half2*)out)[i * 2 + 1] = h23;
}

// W [K,N] fp32 -> WT [N,K] fp16 (or fp32 for g_wkT variant below)
__global__ __launch_bounds__(256)
void transpose_cvt_h(const float* __restrict__ W, __half* __restrict__ WT)
{
    __shared__ float t[32][33];
    const int x = blockIdx.x * 32 + threadIdx.x;
    const int y0 = blockIdx.y * 32 + threadIdx.y;
    #pragma unroll
    for (int i = 0; i < 32; i += 8)
        t[threadIdx.y + i][threadIdx.x] = W[(size_t)(y0 + i) * E_ + x];
    __syncthreads();
    const int x2 = blockIdx.y * 32 + threadIdx.x;
    const int y2 = blockIdx.x * 32 + threadIdx.y;
    #pragma unroll
    for (int i = 0; i < 32; i += 8)
        WT[(size_t)(y2 + i) * E_ + x2] = __float2half_rn(t[threadIdx.x][threadIdx.y + i]);
}

__global__ __launch_bounds__(256)
void transpose_f(const float* __restrict__ W, float* __restrict__ WT)
{
    __shared__ float t[32][33];
    const int x = blockIdx.x * 32 + threadIdx.x;
    const int y0 = blockIdx.y * 32 + threadIdx.y;
    #pragma unroll
    for (int i = 0; i < 32; i += 8)
        t[threadIdx.y + i][threadIdx.x] = W[(size_t)(y0 + i) * E_ + x];
    __syncthreads();
    const int x2 = blockIdx.y * 32 + threadIdx.x;
    const int y2 = blockIdx.x * 32 + threadIdx.y;
    #pragma unroll
    for (int i = 0; i < 32; i += 8)
        WT[(size_t)(y2 + i) * E_ + x2] = t[threadIdx.x][threadIdx.y + i];
}

// ---------------------------------------------------------------------------
// Tiny text projections (fp32)
// ---------------------------------------------------------------------------
__global__ __launch_bounds__(256)
void small_proj(const float* __restrict__ text,
                const float* __restrict__ Wk, const float* __restrict__ bk,
                const float* __restrict__ Wv, const float* __restrict__ bv)
{
    const int b = blockIdx.y;
    const int n = blockIdx.x * 256 + threadIdx.x;
    __shared__ float ts[E_];
    for (int i = threadIdx.x; i < E_; i += 256) ts[i] = text[b * E_ + i];
    __syncthreads();
    float accK = 0.f, accV = 0.f;
    for (int k = 0; k < E_; k++) {
        const float t = ts[k];
        accK += t * Wk[(size_t)k * E_ + n];
        accV += t * Wv[(size_t)k * E_ + n];
    }
    g_kti[b * E_ + n] = accK + bk[n];
    g_vti[b * E_ + n] = accV + bv[n];
}

// ---------------------------------------------------------------------------
// Qt[b][(q*16+l)][e] = fp16( sum_d text[b, q*64+d] * wkT[(l*64+d)][e] )
// ---------------------------------------------------------------------------
__global__ __launch_bounds__(256)
void compute_Q(const float* __restrict__ text)
{
    const int e = blockIdx.x * 256 + threadIdx.x;
    const int ql = blockIdx.y;
    const int q = ql >> 4, l = ql & 15;

    __shared__ float tx[B_][D_];
    for (int i = threadIdx.x; i < B_ * D_; i += 256)
        tx[i / D_][i % D_] = text[(i / D_) * E_ + q * 64 + (i % D_)];
    __syncthreads();

    float acc[B_];
    #pragma unroll
    for (int b = 0; b < B_; b++) acc[b] = 0.f;
    #pragma unroll 8
    for (int d = 0; d < D_; d++) {
        const float w = g_wkT[(size_t)(l * 64 + d) * E_ + e];
        #pragma unroll
        for (int b = 0; b < B_; b++) acc[b] += w * tx[b][d];
    }
    #pragma unroll
    for (int b = 0; b < B_; b++)
        g_Qt[(size_t)b * (256 * E_) + (size_t)ql * E_ + e] = __float2half_rn(acc[b]);
}

// c[b][(q,l)] = sum_d text[b, q*64+d] * b_kit[l*64+d]
__global__ __launch_bounds__(256)
void compute_c(const float* __restrict__ text, const float* __restrict__ bk)
{
    const int b = blockIdx.x;
    const int ql = threadIdx.x;
    const int q = ql >> 4, l = ql & 15;
    float acc = 0.f;
    #pragma unroll 8
    for (int d = 0; d < D_; d++)
        acc += text[b * E_ + q * 64 + d] * bk[l * 64 + d];
    g_c[b * 256 + ql] = acc;
}

// ---------------------------------------------------------------------------
// Pt[b][n][(q*16+l)] = fp16( sum_d v_ti[b, l*64+d] * W_out[(q*64+d)*1024 + n] )
// ---------------------------------------------------------------------------
__global__ __launch_bounds__(256)
void compute_Pt(const float* __restrict__ W_out)
{
    const int n = blockIdx.x * 256 + threadIdx.x;
    const int ql = blockIdx.y;
    const int q = ql >> 4, l = ql & 15;

    __shared__ float vt[B_][D_];
    for (int i = threadIdx.x; i < B_ * D_; i += 256)
        vt[i / D_][i % D_] = g_vti[(i / D_) * E_ + l * 64 + (i % D_)];
    __syncthreads();

    float acc[B_];
    #pragma unroll
    for (int b = 0; b < B_; b++) acc[b] = 0.f;
    #pragma unroll 8
    for (int d = 0; d < D_; d++) {
        const float w = W_out[(size_t)(q * 64 + d) * E_ + n];
        #pragma unroll
        for (int b = 0; b < B_; b++) acc[b] += w * vt[b][d];
    }
    #pragma unroll
    for (int b = 0; b < B_; b++)
        g_Pt[(size_t)b * (E_ * 256) + (size_t)n * 256 + ql] = __float2half_rn(acc[b]);
}

// ---------------------------------------------------------------------------
// Fused per-position attention, 2 positions/block.
// s1 precomputed by the score GEMM (+c correction).
// Writes img_out (fp16) to g_cat and att2 weights (fp16) to g_att2.
// ---------------------------------------------------------------------------
#define NPOS 2
#define PD 65

struct alignas(8) half4 { __half2 a, b; };

__global__ __launch_bounds__(256)
void attention_pos(const float* __restrict__ img)
{
    const int n0 = blockIdx.x * NPOS;
    const int b = blockIdx.y;
    const int tid = threadIdx.x;

    __shared__ float4 xs4[NPOS][256], vs4[NPOS][256];
    __shared__ float ktis[H_ * PD], cb[256];
    __shared__ float att1[NPOS][H_][H_];

    const size_t r0 = (size_t)b * S_ + n0;
    {
        const int e = tid * 4, l = e >> 6, j = e & 63;
        #pragma unroll
        for (int p = 0; p < NPOS; p++) {
            xs4[p][tid] = ((const float4*)img)[(r0 + p) * 256 + tid];
            vs4[p][tid] = ((const float4*)g_vit)[(r0 + p) * 256 + tid];
        }
        float4 vkt = ((const float4*)g_kti)[b * 256 + tid];
        float* kp = &ktis[l * PD + j];
        kp[0] = vkt.x; kp[1] = vkt.y; kp[2] = vkt.z; kp[3] = vkt.w;
        cb[tid] = g_c[b * 256 + tid];
    }
    float s1a = g_s1[(r0 + 0) * 256 + tid];
    float s1b = g_s1[(r0 + 1) * 256 + tid];
    __syncthreads();

    const int q = tid >> 4;
    const int l = tid & 15;
    const float* x0q = (const float*)xs4[0] + q * 64;
    const float* x1q = (const float*)xs4[1] + q * 64;

    s1a = (s1a + cb[tid]) * 0.125f;
    s1b = (s1b + cb[tid]) * 0.125f;

    float s2a = 0.f, s2b = 0.f;
    #pragma unroll
    for (int j = 0; j < D_; j++) {
        const float ktv = ktis[l * PD + j];
        s2a += x0q[j] * ktv;
        s2b += x1q[j] * ktv;
    }
    s2a *= 0.125f; s2b *= 0.125f;

    float m1a = s1a, m1b = s1b, m2a = s2a, m2b = s2b;
    #pragma unroll
    for (int o = 8; o > 0; o >>= 1) {
        m1a = fmaxf(m1a, __shfl_xor_sync(0xffffffffu, m1a, o));
        m1b = fmaxf(m1b, __shfl_xor_sync(0xffffffffu, m1b, o));
        m2a = fmaxf(m2a, __shfl_xor_sync(0xffffffffu, m2a, o));
        m2b = fmaxf(m2b, __shfl_xor_sync(0xffffffffu, m2b, o));
    }
    float e1a = expf(s1a - m1a), e1b = expf(s1b - m1b);
    float e2a = expf(s2a - m2a), e2b = expf(s2b - m2b);
    float z1a = e1a, z1b = e1b, z2a = e2a, z2b = e2b;
    #pragma unroll
    for (int o = 8; o > 0; o >>= 1) {
        z1a += __shfl_xor_sync(0xffffffffu, z1a, o);
        z1b += __shfl_xor_sync(0xffffffffu, z1b, o);
        z2a += __shfl_xor_sync(0xffffffffu, z2a, o);
        z2b += __shfl_xor_sync(0xffffffffu, z2b, o);
    }
    att1[0][q][l] = e1a / z1a;  att1[1][q][l] = e1b / z1b;
    g_att2[(r0 + 0) * 256 + tid] = __float2half_rn(e2a / z2a);
    g_att2[(r0 + 1) * 256 + tid] = __float2half_rn(e2b / z2b);
    __syncthreads();

    const int qq = tid >> 4;
    const int dv = tid & 15;
    half4* cat4 = (half4*)g_cat;
    #pragma unroll
    for (int p = 0; p < NPOS; p++) {
        float4 o1 = make_float4(0.f, 0.f, 0.f, 0.f);
        #pragma unroll
        for (int ll = 0; ll < H_; ll++) {
            const float a1 = att1[p][qq][ll];
            const float4 vv = vs4[p][ll * 16 + dv];
            o1.x += a1 * vv.x; o1.y += a1 * vv.y; o1.z += a1 * vv.z; o1.w += a1 * vv.w;
        }
        half4 h;
        h.a = __floats2half2_rn(o1.x, o1.y);
        h.b = __floats2half2_rn(o1.z, o1.w);
        cat4[(r0 + p) * 256 + tid] = h;
    }
}

// ---------------------------------------------------------------------------
extern "C" void kernel_launch(void* const* d_in, const int* in_sizes, int n_in,
                              void* d_out, int out_size)
{
    const float* img   = (const float*)d_in[0];
    const float* text  = (const float*)d_in[1];
    const float* W_kit = (const float*)d_in[2];
    const float* b_kit = (const float*)d_in[3];
    const float* W_vit = (const float*)d_in[4];
    const float* b_vit = (const float*)d_in[5];
    const float* W_kti = (const float*)d_in[6];
    const float* b_kti = (const float*)d_in[7];
    const float* W_vti = (const float*)d_in[8];
    const float* b_vti = (const float*)d_in[9];
    const float* W_out = (const float*)d_in[10];
    const float* b_out = (const float*)d_in[11];
    float* out = (float*)d_out;

    __half *a16, *cat, *att2, *Qt, *Pt, *wvT, *woT;
    float *vit, *s1, *wkT, *zero;
    cudaGetSymbolAddress((void**)&a16, g_a16);
    cudaGetSymbolAddress((void**)&vit, g_vit);
    cudaGetSymbolAddress((void**)&cat, g_cat);
    cudaGetSymbolAddress((void**)&s1, g_s1);
    cudaGetSymbolAddress((void**)&att2, g_att2);
    cudaGetSymbolAddress((void**)&Qt, g_Qt);
    cudaGetSymbolAddress((void**)&Pt, g_Pt);
    cudaGetSymbolAddress((void**)&wkT, g_wkT);
    cudaGetSymbolAddress((void**)&wvT, g_wvT);
    cudaGetSymbolAddress((void**)&woT, g_woT);
    cudaGetSymbolAddress((void**)&zero, g_zero);

    cudaFuncSetAttribute(gemm_tc, cudaFuncAttributeMaxDynamicSharedMemorySize, GEMM_SMEM);

    // operand preparation
    cvt_img<<<(M1 * E_ / 4) / 256, 256>>>(img, a16);
    transpose_f<<<dim3(32, 32), dim3(32, 8)>>>(W_kit, wkT);
    transpose_cvt_h<<<dim3(32, 32), dim3(32, 8)>>>(W_vit, wvT);
    transpose_cvt_h<<<dim3(32, 32), dim3(32, 8)>>>(W_out, woT);
    small_proj<<<dim3(E_ / 256, B_), 256>>>(text, W_kti, b_kti, W_vti, b_vti);
    compute_Q<<<dim3(4, 256), 256>>>(text);
    compute_c<<<B_, 256>>>(text, b_kit);
    compute_Pt<<<dim3(4, 256), 256>>>(W_out);

    // fused: v_it projection (8 n-tiles) + img-attn scores (2 n-tiles)
    gemm_tc<<<dim3(10, M1 / 128), 128, GEMM_SMEM>>>(
        a16,
        wvT, b_vit, vit, 1024, 0,
        Qt, zero, s1, 256, 256 * E_,
        1024, 8, 32, 4096, 0);

    // fused attention -> img_out (fp16) + att2 weights (fp16)
    attention_pos<<<dim3(S_ / NPOS, B_), 256>>>(img);

    // final projection, img half: rows b*8192 + n
    gemm_tc<<<dim3(8, M1 / 128), 128, GEMM_SMEM>>>(
        cat,
        woT, b_out, out, 1024, 0,
        woT, b_out, out, 1024, 0,
        1024, 8, 32, 8192, 0);

    // final projection, text half (factored): K=256, rows b*8192 + 4096 + n
    gemm_tc<<<dim3(8, M1 / 128), 128, GEMM_SMEM>>>(
        att2,
        Pt, b_out, out, 1024, 256 * E_,
        Pt, b_out, out, 1024, 256 * E_,
        256, 8, 32, 8192, 4096);
}